// round 1
// baseline (speedup 1.0000x reference)
#include <cuda_runtime.h>

#define NMAX 50000
#define EMAX 800000
#define KDIM 256
#define HC   128
#define H    4
#define C    32

// Static scratch (no allocations allowed in kernel_launch).
__device__ float g_W2[KDIM * HC];      // repacked weights [K][H*C]
__device__ float g_h[NMAX * HC];       // projected features [N][H*C]
__device__ float g_asrc[NMAX * H];
__device__ float g_adst[NMAX * H];
__device__ float g_amax[NMAX * H];
__device__ float g_sum[NMAX * H];
__device__ float g_alpha[EMAX * H];    // per-edge logits -> exp values

// ---------------------------------------------------------------------------
// Repack weight [H][K][C] -> W2[K][H*C] for coalesced GEMM B-operand access.
// ---------------------------------------------------------------------------
__global__ void repack_w(const float* __restrict__ w) {
    int idx = blockIdx.x * blockDim.x + threadIdx.x;
    if (idx < H * KDIM * C) {
        int hh = idx / (KDIM * C);
        int f  = (idx / C) % KDIM;
        int c  = idx % C;
        g_W2[f * HC + hh * C + c] = w[idx];
    }
}

// ---------------------------------------------------------------------------
// SGEMM: g_h[M,128] = A[M,256] * g_W2[256,128]
// 128x128 block tile, BK=8, 256 threads, 8x8 per-thread register tile.
// ---------------------------------------------------------------------------
__global__ void gemm128(const float* __restrict__ A, int M) {
    __shared__ float As[8][128];
    __shared__ float Bs[8][128];
    int tid = threadIdx.x;
    int tx = tid & 15, ty = tid >> 4;
    int col0 = tx * 8;
    int blockRow = blockIdx.x * 128;

    float acc[8][8];
    #pragma unroll
    for (int i = 0; i < 8; i++)
        #pragma unroll
        for (int j = 0; j < 8; j++) acc[i][j] = 0.f;

    int aRow = tid >> 1;           // 0..127
    int aCol = (tid & 1) * 4;      // 0 or 4
    int bRow = tid >> 5;           // 0..7
    int bCol = (tid & 31) * 4;     // 0..124

    for (int k0 = 0; k0 < KDIM; k0 += 8) {
        int gr = blockRow + aRow;
        float4 av = make_float4(0.f, 0.f, 0.f, 0.f);
        if (gr < M) av = *(const float4*)(A + (long long)gr * KDIM + k0 + aCol);
        As[aCol + 0][aRow] = av.x;
        As[aCol + 1][aRow] = av.y;
        As[aCol + 2][aRow] = av.z;
        As[aCol + 3][aRow] = av.w;
        *(float4*)&Bs[bRow][bCol] = *(const float4*)(g_W2 + (k0 + bRow) * HC + bCol);
        __syncthreads();
        #pragma unroll
        for (int k = 0; k < 8; k++) {
            float ar[8], br[8];
            #pragma unroll
            for (int i = 0; i < 8; i++) ar[i] = As[k][ty * 8 + i];
            #pragma unroll
            for (int j = 0; j < 8; j++) br[j] = Bs[k][col0 + j];
            #pragma unroll
            for (int i = 0; i < 8; i++)
                #pragma unroll
                for (int j = 0; j < 8; j++)
                    acc[i][j] = fmaf(ar[i], br[j], acc[i][j]);
        }
        __syncthreads();
    }

    #pragma unroll
    for (int i = 0; i < 8; i++) {
        int r = blockRow + ty * 8 + i;
        if (r < M) {
            *(float4*)&g_h[r * HC + col0]     = make_float4(acc[i][0], acc[i][1], acc[i][2], acc[i][3]);
            *(float4*)&g_h[r * HC + col0 + 4] = make_float4(acc[i][4], acc[i][5], acc[i][6], acc[i][7]);
        }
    }
}

// ---------------------------------------------------------------------------
// Per-node attention logits: a_src[n,h] = h[n,h,:].att[h,:C], a_dst with att[h,C:]
// ---------------------------------------------------------------------------
__global__ void logits_kernel(const float* __restrict__ att, int n) {
    int idx = blockIdx.x * blockDim.x + threadIdx.x;
    if (idx < n * H) {
        int node = idx >> 2, hh = idx & 3;
        const float* hp = g_h + node * HC + hh * C;
        const float* a1 = att + hh * 2 * C;
        const float* a2 = a1 + C;
        float s1 = 0.f, s2 = 0.f;
        #pragma unroll
        for (int c = 0; c < C; c++) {
            float v = hp[c];
            s1 = fmaf(v, a1[c], s1);
            s2 = fmaf(v, a2[c], s2);
        }
        g_asrc[idx] = s1;
        g_adst[idx] = s2;
    }
}

// ---------------------------------------------------------------------------
// Init: out = bias (broadcast), amax = -1e9, sum = 0
// ---------------------------------------------------------------------------
__global__ void init_kernel(float* __restrict__ out, const float* __restrict__ bias, int n) {
    int idx = blockIdx.x * blockDim.x + threadIdx.x;
    if (idx < n * HC) out[idx] = bias[idx & (HC - 1)];
    if (idx < n * H) { g_amax[idx] = -1e9f; g_sum[idx] = 0.f; }
}

// Sign-aware float atomic max via integer atomics (no CAS loop).
__device__ __forceinline__ void atomicMaxF(float* addr, float val) {
    if (val >= 0.f) atomicMax((int*)addr, __float_as_int(val));
    else            atomicMin((unsigned int*)addr, __float_as_uint(val));
}

// ---------------------------------------------------------------------------
// Edge pass 1: alpha = LeakyReLU(a_src[src] + a_dst[dst]); segment max by dst
// ---------------------------------------------------------------------------
__global__ void edge1(const int* __restrict__ ei, int e_cnt) {
    int idx = blockIdx.x * blockDim.x + threadIdx.x;
    if (idx < e_cnt * H) {
        int e = idx >> 2, hh = idx & 3;
        int s = ei[e], d = ei[e_cnt + e];
        float al = g_asrc[s * H + hh] + g_adst[d * H + hh];
        al = al > 0.f ? al : 0.2f * al;
        g_alpha[idx] = al;
        atomicMaxF(&g_amax[d * H + hh], al);
    }
}

// ---------------------------------------------------------------------------
// Edge pass 2: exp(alpha - max[dst]); segment sum by dst
// ---------------------------------------------------------------------------
__global__ void edge2(const int* __restrict__ ei, int e_cnt) {
    int idx = blockIdx.x * blockDim.x + threadIdx.x;
    if (idx < e_cnt * H) {
        int e = idx >> 2, hh = idx & 3;
        int d = ei[e_cnt + e];
        float ex = __expf(g_alpha[idx] - g_amax[d * H + hh]);
        g_alpha[idx] = ex;
        atomicAdd(&g_sum[d * H + hh], ex);
    }
}

// ---------------------------------------------------------------------------
// Edge pass 3: out[dst] += h[src] * (exp / (sum[dst]+eps)); one warp per edge,
// each lane handles 4 contiguous channels with a v4 reduction (sm_90+ PTX).
// ---------------------------------------------------------------------------
__global__ void edge3(const int* __restrict__ ei, float* __restrict__ out, int e_cnt) {
    int gid = blockIdx.x * blockDim.x + threadIdx.x;
    int e = gid >> 5;
    if (e >= e_cnt) return;
    int lane = gid & 31;
    int s = ei[e], d = ei[e_cnt + e];
    int hh = lane >> 3;                       // 8 lanes per head (32 ch / 4)
    float a = g_alpha[e * H + hh] / (g_sum[d * H + hh] + 1e-16f);
    float4 hv = *(const float4*)(g_h + s * HC + lane * 4);
    float* dst = out + d * HC + lane * 4;
    asm volatile("red.global.add.v4.f32 [%0], {%1,%2,%3,%4};"
                 :: "l"(dst), "f"(hv.x * a), "f"(hv.y * a), "f"(hv.z * a), "f"(hv.w * a)
                 : "memory");
}

// ---------------------------------------------------------------------------
extern "C" void kernel_launch(void* const* d_in, const int* in_sizes, int n_in,
                              void* d_out, int out_size) {
    const float* x    = (const float*)d_in[0];
    const int*   ei   = (const int*)d_in[1];
    const float* w    = (const float*)d_in[2];
    const float* att  = (const float*)d_in[3];
    const float* bias = (const float*)d_in[4];
    float* out = (float*)d_out;

    int n     = in_sizes[0] / KDIM;   // 50000
    int e_cnt = in_sizes[1] / 2;      // 800000

    repack_w<<<(H * KDIM * C + 255) / 256, 256>>>(w);
    gemm128<<<(n + 127) / 128, 256>>>(x, n);
    logits_kernel<<<(n * H + 255) / 256, 256>>>(att, n);
    init_kernel<<<(n * HC + 255) / 256, 256>>>(out, bias, n);
    edge1<<<(e_cnt * H + 255) / 256, 256>>>(ei, e_cnt);
    edge2<<<(e_cnt * H + 255) / 256, 256>>>(ei, e_cnt);
    edge3<<<(e_cnt * 32 + 255) / 256, 256>>>(ei, out, e_cnt);
}

// round 2
// speedup vs baseline: 1.2299x; 1.2299x over previous
#include <cuda_runtime.h>

#define NMAX 50000
#define EMAX 800000
#define KDIM 256
#define HC   128
#define H    4
#define C    32

// Static scratch (no allocations allowed in kernel_launch).
__device__ __align__(16) float g_W2[KDIM * HC];   // repacked weights [K][H*C]
__device__ __align__(16) float g_h[NMAX * HC];    // projected features [N][H*C]
__device__ __align__(16) float g_asrc[NMAX * H];
__device__ __align__(16) float g_adst[NMAX * H];
__device__ __align__(16) float g_sum[NMAX * H];   // segment sum -> reciprocal
__device__ __align__(16) float g_alpha[EMAX * H]; // per-edge exp values

// ---------------------------------------------------------------------------
// Repack weight [H][K][C] -> W2[K][H*C] for coalesced GEMM B-operand access.
// ---------------------------------------------------------------------------
__global__ void repack_w(const float* __restrict__ w) {
    int idx = blockIdx.x * blockDim.x + threadIdx.x;
    if (idx < H * KDIM * C) {
        int hh = idx / (KDIM * C);
        int f  = (idx / C) % KDIM;
        int c  = idx % C;
        g_W2[f * HC + hh * C + c] = w[idx];
    }
}

// ---------------------------------------------------------------------------
// SGEMM: g_h[M,128] = A[M,256] * g_W2[256,128]
// 128x128 block tile, BK=8, 256 threads, 8x8 per-thread register tile.
// ---------------------------------------------------------------------------
__global__ void gemm128(const float* __restrict__ A, int M) {
    __shared__ float As[8][128];
    __shared__ float Bs[8][128];
    int tid = threadIdx.x;
    int tx = tid & 15, ty = tid >> 4;
    int col0 = tx * 8;
    int blockRow = blockIdx.x * 128;

    float acc[8][8];
    #pragma unroll
    for (int i = 0; i < 8; i++)
        #pragma unroll
        for (int j = 0; j < 8; j++) acc[i][j] = 0.f;

    int aRow = tid >> 1;           // 0..127
    int aCol = (tid & 1) * 4;      // 0 or 4
    int bRow = tid >> 5;           // 0..7
    int bCol = (tid & 31) * 4;     // 0..124

    for (int k0 = 0; k0 < KDIM; k0 += 8) {
        int gr = blockRow + aRow;
        float4 av = make_float4(0.f, 0.f, 0.f, 0.f);
        if (gr < M) av = *(const float4*)(A + (long long)gr * KDIM + k0 + aCol);
        As[aCol + 0][aRow] = av.x;
        As[aCol + 1][aRow] = av.y;
        As[aCol + 2][aRow] = av.z;
        As[aCol + 3][aRow] = av.w;
        *(float4*)&Bs[bRow][bCol] = *(const float4*)(g_W2 + (k0 + bRow) * HC + bCol);
        __syncthreads();
        #pragma unroll
        for (int k = 0; k < 8; k++) {
            float ar[8], br[8];
            #pragma unroll
            for (int i = 0; i < 8; i++) ar[i] = As[k][ty * 8 + i];
            #pragma unroll
            for (int j = 0; j < 8; j++) br[j] = Bs[k][col0 + j];
            #pragma unroll
            for (int i = 0; i < 8; i++)
                #pragma unroll
                for (int j = 0; j < 8; j++)
                    acc[i][j] = fmaf(ar[i], br[j], acc[i][j]);
        }
        __syncthreads();
    }

    #pragma unroll
    for (int i = 0; i < 8; i++) {
        int r = blockRow + ty * 8 + i;
        if (r < M) {
            *(float4*)&g_h[r * HC + col0]     = make_float4(acc[i][0], acc[i][1], acc[i][2], acc[i][3]);
            *(float4*)&g_h[r * HC + col0 + 4] = make_float4(acc[i][4], acc[i][5], acc[i][6], acc[i][7]);
        }
    }
}

// ---------------------------------------------------------------------------
// Per-node attention logits: a_src[n,h] = h[n,h,:].att[h,:C], a_dst with att[h,C:]
// ---------------------------------------------------------------------------
__global__ void logits_kernel(const float* __restrict__ att, int n) {
    int idx = blockIdx.x * blockDim.x + threadIdx.x;
    if (idx < n * H) {
        int node = idx >> 2, hh = idx & 3;
        const float* hp = g_h + node * HC + hh * C;
        const float* a1 = att + hh * 2 * C;
        const float* a2 = a1 + C;
        float s1 = 0.f, s2 = 0.f;
        #pragma unroll
        for (int c = 0; c < C; c++) {
            float v = hp[c];
            s1 = fmaf(v, a1[c], s1);
            s2 = fmaf(v, a2[c], s2);
        }
        g_asrc[idx] = s1;
        g_adst[idx] = s2;
    }
}

// ---------------------------------------------------------------------------
// Vectorized init: out = bias (broadcast, float4), sum = 0
// ---------------------------------------------------------------------------
__global__ void init_kernel(float4* __restrict__ out, const float* __restrict__ bias, int n) {
    int idx = blockIdx.x * blockDim.x + threadIdx.x;
    int nv = n * (HC / 4);
    if (idx < nv) {
        int c4 = (idx & (HC / 4 - 1)) * 4;
        out[idx] = make_float4(bias[c4], bias[c4 + 1], bias[c4 + 2], bias[c4 + 3]);
    }
    if (idx < n) *(float4*)&g_sum[idx * 4] = make_float4(0.f, 0.f, 0.f, 0.f);
}

// ---------------------------------------------------------------------------
// Fused edge pass: alpha = exp(LeakyReLU(a_src[s]+a_dst[d])) for all 4 heads,
// one thread per edge, single v4 reduction into g_sum[d*4].
// (Max subtraction dropped: softmax is shift-invariant; logits are O(1).)
// ---------------------------------------------------------------------------
__global__ void edge12(const int* __restrict__ ei, int e_cnt) {
    int e = blockIdx.x * blockDim.x + threadIdx.x;
    if (e >= e_cnt) return;
    int s = ei[e], d = ei[e_cnt + e];
    float4 as = *(const float4*)&g_asrc[s * 4];
    float4 ad = *(const float4*)&g_adst[d * 4];
    float a0 = as.x + ad.x, a1 = as.y + ad.y, a2 = as.z + ad.z, a3 = as.w + ad.w;
    a0 = a0 > 0.f ? a0 : 0.2f * a0;
    a1 = a1 > 0.f ? a1 : 0.2f * a1;
    a2 = a2 > 0.f ? a2 : 0.2f * a2;
    a3 = a3 > 0.f ? a3 : 0.2f * a3;
    float e0 = __expf(a0), e1 = __expf(a1), e2 = __expf(a2), e3 = __expf(a3);
    *(float4*)&g_alpha[e * 4] = make_float4(e0, e1, e2, e3);
    asm volatile("red.global.add.v4.f32 [%0], {%1,%2,%3,%4};"
                 :: "l"(&g_sum[d * 4]), "f"(e0), "f"(e1), "f"(e2), "f"(e3)
                 : "memory");
}

// ---------------------------------------------------------------------------
// Reciprocal of segment sums: g_sum[i] = 1/(g_sum[i]+eps)
// ---------------------------------------------------------------------------
__global__ void rinv_kernel(int n) {
    int idx = blockIdx.x * blockDim.x + threadIdx.x;
    if (idx < n * H) g_sum[idx] = __frcp_rn(g_sum[idx] + 1e-16f);
}

// ---------------------------------------------------------------------------
// Aggregation: out[dst] += h[src] * (alpha * rinv[dst]); one warp per edge,
// each lane handles 4 contiguous channels with a v4 reduction.
// ---------------------------------------------------------------------------
__global__ void edge3(const int* __restrict__ ei, float* __restrict__ out, int e_cnt) {
    int gid = blockIdx.x * blockDim.x + threadIdx.x;
    int e = gid >> 5;
    if (e >= e_cnt) return;
    int lane = gid & 31;
    int s = ei[e], d = ei[e_cnt + e];
    int hh = lane >> 3;                       // 8 lanes per head (32 ch / 4)
    float a = g_alpha[e * 4 + hh] * g_sum[d * 4 + hh];
    float4 hv = *(const float4*)(g_h + s * HC + lane * 4);
    float* dst = out + d * HC + lane * 4;
    asm volatile("red.global.add.v4.f32 [%0], {%1,%2,%3,%4};"
                 :: "l"(dst), "f"(hv.x * a), "f"(hv.y * a), "f"(hv.z * a), "f"(hv.w * a)
                 : "memory");
}

// ---------------------------------------------------------------------------
extern "C" void kernel_launch(void* const* d_in, const int* in_sizes, int n_in,
                              void* d_out, int out_size) {
    const float* x    = (const float*)d_in[0];
    const int*   ei   = (const int*)d_in[1];
    const float* w    = (const float*)d_in[2];
    const float* att  = (const float*)d_in[3];
    const float* bias = (const float*)d_in[4];
    float* out = (float*)d_out;

    int n     = in_sizes[0] / KDIM;   // 50000
    int e_cnt = in_sizes[1] / 2;      // 800000

    repack_w<<<(H * KDIM * C + 255) / 256, 256>>>(w);
    gemm128<<<(n + 127) / 128, 256>>>(x, n);
    logits_kernel<<<(n * H + 255) / 256, 256>>>(att, n);
    init_kernel<<<(n * (HC / 4) + 255) / 256, 256>>>((float4*)out, bias, n);
    edge12<<<(e_cnt + 255) / 256, 256>>>(ei, e_cnt);
    rinv_kernel<<<(n * H + 255) / 256, 256>>>(n);
    edge3<<<(e_cnt * 32 + 255) / 256, 256>>>(ei, out, e_cnt);
}

// round 3
// speedup vs baseline: 1.2301x; 1.0001x over previous
#include <cuda_runtime.h>

#define NMAX 50000
#define EMAX 800000
#define KDIM 256
#define HC   128
#define H    4
#define C    32

// Static scratch (no allocations allowed in kernel_launch).
__device__ __align__(16) float g_W2[KDIM * HC];   // repacked weights [K][H*C]
__device__ __align__(16) float g_h[NMAX * HC];    // projected features [N][H*C]
__device__ __align__(16) float g_asrc[NMAX * H];
__device__ __align__(16) float g_adst[NMAX * H];
__device__ __align__(16) float g_alpha[EMAX * H]; // exp(alpha), CSR slot order
__device__ int g_cnt[NMAX];                       // in-degree (after hist)
__device__ int g_offs[NMAX];                      // CSR offsets (exclusive scan)
__device__ int g_rank[EMAX];                      // edge rank within its dst
__device__ int g_psrc[EMAX];                      // src node id, CSR slot order

// ---------------------------------------------------------------------------
// Repack weight [H][K][C] -> W2[K][H*C]; also zero g_cnt.
// ---------------------------------------------------------------------------
__global__ void repack_w(const float* __restrict__ w) {
    int idx = blockIdx.x * blockDim.x + threadIdx.x;
    if (idx < H * KDIM * C) {
        int hh = idx / (KDIM * C);
        int f  = (idx / C) % KDIM;
        int c  = idx % C;
        g_W2[f * HC + hh * C + c] = w[idx];
    }
    if (idx < NMAX) g_cnt[idx] = 0;
}

// ---------------------------------------------------------------------------
// SGEMM: g_h[M,128] = A[M,256] * g_W2[256,128]
// 128x128 tile, BK=8, 256 threads, 8x8 register tile, double-buffered smem.
// ---------------------------------------------------------------------------
__global__ void gemm128(const float* __restrict__ A, int M) {
    __shared__ float As[2][8][128];
    __shared__ float Bs[2][8][128];
    int tid = threadIdx.x;
    int tx = tid & 15, ty = tid >> 4;
    int col0 = tx * 8;
    int blockRow = blockIdx.x * 128;

    float acc[8][8];
    #pragma unroll
    for (int i = 0; i < 8; i++)
        #pragma unroll
        for (int j = 0; j < 8; j++) acc[i][j] = 0.f;

    int aRow = tid >> 1;           // 0..127
    int aCol = (tid & 1) * 4;      // 0 or 4
    int bRow = tid >> 5;           // 0..7
    int bCol = (tid & 31) * 4;     // 0..124
    int gr = blockRow + aRow;
    const float* aPtr = A + (long long)gr * KDIM + aCol;

    // Preload tile 0 into buffer 0.
    float4 av = make_float4(0.f, 0.f, 0.f, 0.f);
    if (gr < M) av = *(const float4*)(aPtr);
    float4 bv = *(const float4*)(g_W2 + bRow * HC + bCol);
    As[0][aCol + 0][aRow] = av.x;
    As[0][aCol + 1][aRow] = av.y;
    As[0][aCol + 2][aRow] = av.z;
    As[0][aCol + 3][aRow] = av.w;
    *(float4*)&Bs[0][bRow][bCol] = bv;
    __syncthreads();

    int buf = 0;
    for (int k0 = 0; k0 < KDIM; k0 += 8) {
        bool has_next = (k0 + 8) < KDIM;
        if (has_next) {
            av = make_float4(0.f, 0.f, 0.f, 0.f);
            if (gr < M) av = *(const float4*)(aPtr + k0 + 8);
            bv = *(const float4*)(g_W2 + (k0 + 8 + bRow) * HC + bCol);
        }
        #pragma unroll
        for (int k = 0; k < 8; k++) {
            float ar[8], br[8];
            #pragma unroll
            for (int i = 0; i < 8; i++) ar[i] = As[buf][k][ty * 8 + i];
            #pragma unroll
            for (int j = 0; j < 8; j++) br[j] = Bs[buf][k][col0 + j];
            #pragma unroll
            for (int i = 0; i < 8; i++)
                #pragma unroll
                for (int j = 0; j < 8; j++)
                    acc[i][j] = fmaf(ar[i], br[j], acc[i][j]);
        }
        if (has_next) {
            int nb = buf ^ 1;
            As[nb][aCol + 0][aRow] = av.x;
            As[nb][aCol + 1][aRow] = av.y;
            As[nb][aCol + 2][aRow] = av.z;
            As[nb][aCol + 3][aRow] = av.w;
            *(float4*)&Bs[nb][bRow][bCol] = bv;
            __syncthreads();
            buf = nb;
        }
    }

    #pragma unroll
    for (int i = 0; i < 8; i++) {
        int r = blockRow + ty * 8 + i;
        if (r < M) {
            *(float4*)&g_h[r * HC + col0]     = make_float4(acc[i][0], acc[i][1], acc[i][2], acc[i][3]);
            *(float4*)&g_h[r * HC + col0 + 4] = make_float4(acc[i][4], acc[i][5], acc[i][6], acc[i][7]);
        }
    }
}

// ---------------------------------------------------------------------------
// Per-node attention logits.
// ---------------------------------------------------------------------------
__global__ void logits_kernel(const float* __restrict__ att, int n) {
    int idx = blockIdx.x * blockDim.x + threadIdx.x;
    if (idx < n * H) {
        int node = idx >> 2, hh = idx & 3;
        const float* hp = g_h + node * HC + hh * C;
        const float* a1 = att + hh * 2 * C;
        const float* a2 = a1 + C;
        float s1 = 0.f, s2 = 0.f;
        #pragma unroll
        for (int c = 0; c < C; c++) {
            float v = hp[c];
            s1 = fmaf(v, a1[c], s1);
            s2 = fmaf(v, a2[c], s2);
        }
        g_asrc[idx] = s1;
        g_adst[idx] = s2;
    }
}

// ---------------------------------------------------------------------------
// Histogram: in-degree per dst + per-edge rank within its dst.
// ---------------------------------------------------------------------------
__global__ void hist_kernel(const int* __restrict__ ei, int e_cnt) {
    int e = blockIdx.x * blockDim.x + threadIdx.x;
    if (e < e_cnt) {
        int d = ei[e_cnt + e];
        g_rank[e] = atomicAdd(&g_cnt[d], 1);
    }
}

// ---------------------------------------------------------------------------
// Exclusive scan of g_cnt -> g_offs (single block, 1024 threads, chunked).
// ---------------------------------------------------------------------------
__global__ void scan_kernel(int n) {
    __shared__ int sh[1024];
    int t = threadIdx.x;
    int chunk = (n + 1023) / 1024;
    int start = t * chunk;
    int stop = min(start + chunk, n);
    int s = 0;
    for (int i = start; i < stop; i++) s += g_cnt[i];
    sh[t] = s;
    __syncthreads();
    // Hillis-Steele inclusive scan
    for (int off = 1; off < 1024; off <<= 1) {
        int v = (t >= off) ? sh[t - off] : 0;
        __syncthreads();
        sh[t] += v;
        __syncthreads();
    }
    int run = (t > 0) ? sh[t - 1] : 0;
    for (int i = start; i < stop; i++) {
        g_offs[i] = run;
        run += g_cnt[i];
    }
}

// ---------------------------------------------------------------------------
// Fused edge pass: exp(LeakyReLU(a_src[s]+a_dst[d])) for 4 heads, written
// directly into CSR slot order along with the src id.
// (Max subtraction dropped: softmax is shift-invariant; logits are O(1).)
// ---------------------------------------------------------------------------
__global__ void edge12(const int* __restrict__ ei, int e_cnt) {
    int e = blockIdx.x * blockDim.x + threadIdx.x;
    if (e >= e_cnt) return;
    int s = ei[e], d = ei[e_cnt + e];
    int slot = g_offs[d] + g_rank[e];
    float4 as = *(const float4*)&g_asrc[s * 4];
    float4 ad = *(const float4*)&g_adst[d * 4];
    float a0 = as.x + ad.x, a1 = as.y + ad.y, a2 = as.z + ad.z, a3 = as.w + ad.w;
    a0 = a0 > 0.f ? a0 : 0.2f * a0;
    a1 = a1 > 0.f ? a1 : 0.2f * a1;
    a2 = a2 > 0.f ? a2 : 0.2f * a2;
    a3 = a3 > 0.f ? a3 : 0.2f * a3;
    *(float4*)&g_alpha[slot * 4] =
        make_float4(__expf(a0), __expf(a1), __expf(a2), __expf(a3));
    g_psrc[slot] = s;
}

// ---------------------------------------------------------------------------
// Gather aggregation: one warp per dst node. Sequential alpha/src reads,
// random h gathers, single non-atomic write (bias folded in).
// out[d] = (sum_e h[src_e]*alpha_e) / (sum_e alpha_e + eps) + bias
// ---------------------------------------------------------------------------
__global__ void agg_kernel(float* __restrict__ out, const float* __restrict__ bias, int n) {
    int gid = blockIdx.x * blockDim.x + threadIdx.x;
    int node = gid >> 5;
    if (node >= n) return;
    int lane = gid & 31;
    int hh = lane >> 3;
    int beg = g_offs[node];
    int end = beg + g_cnt[node];
    float4 acc = make_float4(0.f, 0.f, 0.f, 0.f);
    float asum = 0.f;
    for (int i = beg; i < end; i++) {
        int s = g_psrc[i];
        float a = g_alpha[i * 4 + hh];
        asum += a;
        float4 hv = *(const float4*)(g_h + s * HC + lane * 4);
        acc.x = fmaf(hv.x, a, acc.x);
        acc.y = fmaf(hv.y, a, acc.y);
        acc.z = fmaf(hv.z, a, acc.z);
        acc.w = fmaf(hv.w, a, acc.w);
    }
    float r = __frcp_rn(asum + 1e-16f);
    const float4 bv = *(const float4*)(bias + lane * 4);
    float4 o = make_float4(fmaf(acc.x, r, bv.x), fmaf(acc.y, r, bv.y),
                           fmaf(acc.z, r, bv.z), fmaf(acc.w, r, bv.w));
    *(float4*)(out + node * HC + lane * 4) = o;
}

// ---------------------------------------------------------------------------
extern "C" void kernel_launch(void* const* d_in, const int* in_sizes, int n_in,
                              void* d_out, int out_size) {
    const float* x    = (const float*)d_in[0];
    const int*   ei   = (const int*)d_in[1];
    const float* w    = (const float*)d_in[2];
    const float* att  = (const float*)d_in[3];
    const float* bias = (const float*)d_in[4];
    float* out = (float*)d_out;

    int n     = in_sizes[0] / KDIM;   // 50000
    int e_cnt = in_sizes[1] / 2;      // 800000

    repack_w<<<(NMAX + 255) / 256, 256>>>(w);
    gemm128<<<(n + 127) / 128, 256>>>(x, n);
    hist_kernel<<<(e_cnt + 255) / 256, 256>>>(ei, e_cnt);
    logits_kernel<<<(n * H + 255) / 256, 256>>>(att, n);
    scan_kernel<<<1, 1024>>>(n);
    edge12<<<(e_cnt + 255) / 256, 256>>>(ei, e_cnt);
    agg_kernel<<<(n * 32 + 255) / 256, 256>>>(out, bias, n);
}

// round 4
// speedup vs baseline: 1.3901x; 1.1301x over previous
#include <cuda_runtime.h>

#define NMAX 50000
#define EMAX 800000
#define KDIM 256
#define HC   128
#define H    4
#define C    32

// Static scratch (no allocations allowed in kernel_launch).
__device__ __align__(16) float g_h[NMAX * HC];    // projected features [N][H*C]
__device__ __align__(16) float g_asrc[NMAX * H];
__device__ __align__(16) float g_adst[NMAX * H];
__device__ __align__(16) float g_alpha[EMAX * H]; // exp(alpha), CSR slot order
__device__ int g_cnt[NMAX];                       // in-degree (after hist)
__device__ int g_offs[NMAX];                      // CSR offsets (exclusive scan)
__device__ int g_rank[EMAX];                      // edge rank within its dst
__device__ int g_psrc[EMAX];                      // src node id, CSR slot order

// ---------------------------------------------------------------------------
// Phase 1 (block-specialized):
//  blocks [0, nGemm): SGEMM g_h[M,128] = A[M,256] * W (direct per-head load),
//    128x128 tile, BK=8, 256 threads, 8x8 register tile, double-buffered,
//    with the attention-logit dot products fused into the epilogue.
//  blocks [nGemm, ...): in-degree histogram + per-edge rank (rides gemm tail).
// ---------------------------------------------------------------------------
__global__ void phase1(const float* __restrict__ A, const float* __restrict__ w,
                       const float* __restrict__ att, const int* __restrict__ ei,
                       int M, int e_cnt, int nGemm) {
    if (blockIdx.x >= nGemm) {
        int e = (blockIdx.x - nGemm) * blockDim.x + threadIdx.x;
        if (e < e_cnt) {
            int d = ei[e_cnt + e];
            g_rank[e] = atomicAdd(&g_cnt[d], 1);
        }
        return;
    }

    __shared__ float As[2][8][128];
    __shared__ float Bs[2][8][128];
    int tid = threadIdx.x;
    int tx = tid & 15, ty = tid >> 4;
    int col0 = tx * 8;
    int blockRow = blockIdx.x * 128;

    float acc[8][8];
    #pragma unroll
    for (int i = 0; i < 8; i++)
        #pragma unroll
        for (int j = 0; j < 8; j++) acc[i][j] = 0.f;

    int aRow = tid >> 1;           // 0..127
    int aCol = (tid & 1) * 4;      // 0 or 4
    int bRow = tid >> 5;           // 0..7
    int bCol = (tid & 31) * 4;     // 0..124
    int gr = blockRow + aRow;
    const float* aPtr = A + (long long)gr * KDIM + aCol;
    // B element (k, bCol) = w[(bCol/32)*KDIM*C + k*C + (bCol%32)]
    const float* wPtr = w + (bCol >> 5) * (KDIM * C) + (bCol & 31);

    // Preload tile 0 into buffer 0.
    float4 av = make_float4(0.f, 0.f, 0.f, 0.f);
    if (gr < M) av = *(const float4*)(aPtr);
    float4 bv = *(const float4*)(wPtr + bRow * C);
    As[0][aCol + 0][aRow] = av.x;
    As[0][aCol + 1][aRow] = av.y;
    As[0][aCol + 2][aRow] = av.z;
    As[0][aCol + 3][aRow] = av.w;
    *(float4*)&Bs[0][bRow][bCol] = bv;
    __syncthreads();

    int buf = 0;
    for (int k0 = 0; k0 < KDIM; k0 += 8) {
        bool has_next = (k0 + 8) < KDIM;
        if (has_next) {
            av = make_float4(0.f, 0.f, 0.f, 0.f);
            if (gr < M) av = *(const float4*)(aPtr + k0 + 8);
            bv = *(const float4*)(wPtr + (k0 + 8 + bRow) * C);
        }
        #pragma unroll
        for (int k = 0; k < 8; k++) {
            float ar[8], br[8];
            #pragma unroll
            for (int i = 0; i < 8; i++) ar[i] = As[buf][k][ty * 8 + i];
            #pragma unroll
            for (int j = 0; j < 8; j++) br[j] = Bs[buf][k][col0 + j];
            #pragma unroll
            for (int i = 0; i < 8; i++)
                #pragma unroll
                for (int j = 0; j < 8; j++)
                    acc[i][j] = fmaf(ar[i], br[j], acc[i][j]);
        }
        if (has_next) {
            int nb = buf ^ 1;
            As[nb][aCol + 0][aRow] = av.x;
            As[nb][aCol + 1][aRow] = av.y;
            As[nb][aCol + 2][aRow] = av.z;
            As[nb][aCol + 3][aRow] = av.w;
            *(float4*)&Bs[nb][bRow][bCol] = bv;
            __syncthreads();
            buf = nb;
        }
    }

    // Store h tile.
    #pragma unroll
    for (int i = 0; i < 8; i++) {
        int r = blockRow + ty * 8 + i;
        if (r < M) {
            *(float4*)&g_h[r * HC + col0]     = make_float4(acc[i][0], acc[i][1], acc[i][2], acc[i][3]);
            *(float4*)&g_h[r * HC + col0 + 4] = make_float4(acc[i][4], acc[i][5], acc[i][6], acc[i][7]);
        }
    }

    // Fused attention logits: this thread's 8 columns are channels
    // [j0, j0+8) of head (tx>>2). Reduce across the aligned 4-lane group.
    int head = tx >> 2;
    int j0 = (tx & 3) * 8;
    float attS[8], attD[8];
    #pragma unroll
    for (int j = 0; j < 8; j++) {
        attS[j] = __ldg(att + head * (2 * C) + j0 + j);
        attD[j] = __ldg(att + head * (2 * C) + C + j0 + j);
    }
    #pragma unroll
    for (int i = 0; i < 8; i++) {
        float s1 = 0.f, s2 = 0.f;
        #pragma unroll
        for (int j = 0; j < 8; j++) {
            s1 = fmaf(acc[i][j], attS[j], s1);
            s2 = fmaf(acc[i][j], attD[j], s2);
        }
        s1 += __shfl_xor_sync(0xffffffffu, s1, 1);
        s1 += __shfl_xor_sync(0xffffffffu, s1, 2);
        s2 += __shfl_xor_sync(0xffffffffu, s2, 1);
        s2 += __shfl_xor_sync(0xffffffffu, s2, 2);
        if ((tx & 3) == 0) {
            int r = blockRow + ty * 8 + i;
            if (r < M) {
                g_asrc[r * H + head] = s1;
                g_adst[r * H + head] = s2;
            }
        }
    }
}

// ---------------------------------------------------------------------------
// Exclusive scan of g_cnt -> g_offs (single block, 1024 threads, chunked).
// ---------------------------------------------------------------------------
__global__ void scan_kernel(int n) {
    __shared__ int sh[1024];
    int t = threadIdx.x;
    int chunk = (n + 1023) / 1024;
    int start = t * chunk;
    int stop = min(start + chunk, n);
    int s = 0;
    for (int i = start; i < stop; i++) s += g_cnt[i];
    sh[t] = s;
    __syncthreads();
    for (int off = 1; off < 1024; off <<= 1) {
        int v = (t >= off) ? sh[t - off] : 0;
        __syncthreads();
        sh[t] += v;
        __syncthreads();
    }
    int run = (t > 0) ? sh[t - 1] : 0;
    for (int i = start; i < stop; i++) {
        g_offs[i] = run;
        run += g_cnt[i];
    }
}

// ---------------------------------------------------------------------------
// Fused edge pass: exp(LeakyReLU(a_src[s]+a_dst[d])) for 4 heads, written
// directly into CSR slot order along with the src id.
// (Max subtraction dropped: softmax is shift-invariant; logits are O(1).)
// ---------------------------------------------------------------------------
__global__ void edge12(const int* __restrict__ ei, int e_cnt) {
    int e = blockIdx.x * blockDim.x + threadIdx.x;
    if (e >= e_cnt) return;
    int s = ei[e], d = ei[e_cnt + e];
    int slot = g_offs[d] + g_rank[e];
    float4 as = *(const float4*)&g_asrc[s * 4];
    float4 ad = *(const float4*)&g_adst[d * 4];
    float a0 = as.x + ad.x, a1 = as.y + ad.y, a2 = as.z + ad.z, a3 = as.w + ad.w;
    a0 = a0 > 0.f ? a0 : 0.2f * a0;
    a1 = a1 > 0.f ? a1 : 0.2f * a1;
    a2 = a2 > 0.f ? a2 : 0.2f * a2;
    a3 = a3 > 0.f ? a3 : 0.2f * a3;
    *(float4*)&g_alpha[slot * 4] =
        make_float4(__expf(a0), __expf(a1), __expf(a2), __expf(a3));
    g_psrc[slot] = s;
}

// ---------------------------------------------------------------------------
// Gather aggregation: one warp per dst node, unrolled x4 for memory-level
// parallelism (4 independent psrc/alpha/h load batches in flight).
// out[d] = (sum_e h[src_e]*alpha_e) / (sum_e alpha_e + eps) + bias
// ---------------------------------------------------------------------------
__global__ void agg_kernel(float* __restrict__ out, const float* __restrict__ bias, int n) {
    int gid = blockIdx.x * blockDim.x + threadIdx.x;
    int node = gid >> 5;
    if (node >= n) return;
    int lane = gid & 31;
    int hh = lane >> 3;
    int beg = g_offs[node];
    int end = beg + g_cnt[node];
    float4 acc = make_float4(0.f, 0.f, 0.f, 0.f);
    float asum = 0.f;
    int i = beg;
    for (; i + 4 <= end; i += 4) {
        int s0 = __ldg(&g_psrc[i]);
        int s1 = __ldg(&g_psrc[i + 1]);
        int s2 = __ldg(&g_psrc[i + 2]);
        int s3 = __ldg(&g_psrc[i + 3]);
        float a0 = __ldg(&g_alpha[i * 4 + hh]);
        float a1 = __ldg(&g_alpha[(i + 1) * 4 + hh]);
        float a2 = __ldg(&g_alpha[(i + 2) * 4 + hh]);
        float a3 = __ldg(&g_alpha[(i + 3) * 4 + hh]);
        float4 h0 = *(const float4*)(g_h + s0 * HC + lane * 4);
        float4 h1 = *(const float4*)(g_h + s1 * HC + lane * 4);
        float4 h2 = *(const float4*)(g_h + s2 * HC + lane * 4);
        float4 h3 = *(const float4*)(g_h + s3 * HC + lane * 4);
        asum += (a0 + a1) + (a2 + a3);
        acc.x = fmaf(h0.x, a0, acc.x); acc.y = fmaf(h0.y, a0, acc.y);
        acc.z = fmaf(h0.z, a0, acc.z); acc.w = fmaf(h0.w, a0, acc.w);
        acc.x = fmaf(h1.x, a1, acc.x); acc.y = fmaf(h1.y, a1, acc.y);
        acc.z = fmaf(h1.z, a1, acc.z); acc.w = fmaf(h1.w, a1, acc.w);
        acc.x = fmaf(h2.x, a2, acc.x); acc.y = fmaf(h2.y, a2, acc.y);
        acc.z = fmaf(h2.z, a2, acc.z); acc.w = fmaf(h2.w, a2, acc.w);
        acc.x = fmaf(h3.x, a3, acc.x); acc.y = fmaf(h3.y, a3, acc.y);
        acc.z = fmaf(h3.z, a3, acc.z); acc.w = fmaf(h3.w, a3, acc.w);
    }
    for (; i < end; i++) {
        int s = __ldg(&g_psrc[i]);
        float a = __ldg(&g_alpha[i * 4 + hh]);
        asum += a;
        float4 hv = *(const float4*)(g_h + s * HC + lane * 4);
        acc.x = fmaf(hv.x, a, acc.x);
        acc.y = fmaf(hv.y, a, acc.y);
        acc.z = fmaf(hv.z, a, acc.z);
        acc.w = fmaf(hv.w, a, acc.w);
    }
    float r = __frcp_rn(asum + 1e-16f);
    const float4 bv = *(const float4*)(bias + lane * 4);
    float4 o = make_float4(fmaf(acc.x, r, bv.x), fmaf(acc.y, r, bv.y),
                           fmaf(acc.z, r, bv.z), fmaf(acc.w, r, bv.w));
    *(float4*)(out + node * HC + lane * 4) = o;
}

// ---------------------------------------------------------------------------
extern "C" void kernel_launch(void* const* d_in, const int* in_sizes, int n_in,
                              void* d_out, int out_size) {
    const float* x    = (const float*)d_in[0];
    const int*   ei   = (const int*)d_in[1];
    const float* w    = (const float*)d_in[2];
    const float* att  = (const float*)d_in[3];
    const float* bias = (const float*)d_in[4];
    float* out = (float*)d_out;

    int n     = in_sizes[0] / KDIM;   // 50000
    int e_cnt = in_sizes[1] / 2;      // 800000

    void* cnt_ptr = nullptr;
    cudaGetSymbolAddress(&cnt_ptr, g_cnt);
    cudaMemsetAsync(cnt_ptr, 0, NMAX * sizeof(int));

    int nGemm = (n + 127) / 128;
    int nHist = (e_cnt + 255) / 256;
    phase1<<<nGemm + nHist, 256>>>(x, w, att, ei, n, e_cnt, nGemm);
    scan_kernel<<<1, 1024>>>(n);
    edge12<<<(e_cnt + 255) / 256, 256>>>(ei, e_cnt);
    agg_kernel<<<(n * 32 + 255) / 256, 256>>>(out, bias, n);
}

// round 5
// speedup vs baseline: 1.6092x; 1.1576x over previous
#include <cuda_runtime.h>
#include <cuda_bf16.h>
#include <cstdint>

#define NMAX 50000
#define EMAX 800000
#define KDIM 256
#define HC   128
#define H    4
#define C    32

// Static scratch (no allocations allowed in kernel_launch).
__device__ __align__(16) float g_h[NMAX * HC];    // projected features [N][H*C]
__device__ __align__(16) float g_asrc[NMAX * H];
__device__ __align__(16) float g_adst[NMAX * H];
__device__ __align__(16) float g_alpha[EMAX * H]; // exp(alpha), CSR slot order
__device__ int g_cnt[NMAX];                       // in-degree (after hist)
__device__ int g_offs[NMAX];                      // CSR offsets (exclusive scan)
__device__ int g_rank[EMAX];                      // edge rank within its dst
__device__ int g_psrc[EMAX];                      // src node id, CSR slot order

// ---------------------------------------------------------------------------
// PTX helpers
// ---------------------------------------------------------------------------
__device__ __forceinline__ uint32_t s2u(const void* p) {
    uint32_t a;
    asm("{ .reg .u64 t; cvta.to.shared.u64 t, %1; cvt.u32.u64 %0, t; }"
        : "=r"(a) : "l"(p));
    return a;
}

#define LDSM4(r, addr)                                                        \
    asm volatile("ldmatrix.sync.aligned.m8n8.x4.shared.b16 {%0,%1,%2,%3}, [%4];" \
                 : "=r"((r)[0]), "=r"((r)[1]), "=r"((r)[2]), "=r"((r)[3])     \
                 : "r"(addr))

#define LDSM4T(r, addr)                                                       \
    asm volatile("ldmatrix.sync.aligned.m8n8.x4.trans.shared.b16 {%0,%1,%2,%3}, [%4];" \
                 : "=r"((r)[0]), "=r"((r)[1]), "=r"((r)[2]), "=r"((r)[3])     \
                 : "r"(addr))

#define MMA_BF16(c, a, b0, b1)                                                \
    asm volatile("mma.sync.aligned.m16n8k16.row.col.f32.bf16.bf16.f32 "       \
                 "{%0,%1,%2,%3}, {%4,%5,%6,%7}, {%8,%9}, {%0,%1,%2,%3};"      \
                 : "+f"((c)[0]), "+f"((c)[1]), "+f"((c)[2]), "+f"((c)[3])     \
                 : "r"((a)[0]), "r"((a)[1]), "r"((a)[2]), "r"((a)[3]),        \
                   "r"(b0), "r"(b1))

__device__ __forceinline__ uint32_t pack2(float a, float b, float& loa, float& lob) {
    __nv_bfloat16 ha = __float2bfloat16_rn(a);
    __nv_bfloat16 hb = __float2bfloat16_rn(b);
    loa = a - __bfloat162float(ha);
    lob = b - __bfloat162float(hb);
    __nv_bfloat162 p;
    p.x = ha; p.y = hb;
    return *(uint32_t*)&p;
}
__device__ __forceinline__ uint32_t pack2lo(float a, float b) {
    __nv_bfloat162 p;
    p.x = __float2bfloat16_rn(a);
    p.y = __float2bfloat16_rn(b);
    return *(uint32_t*)&p;
}

// ---------------------------------------------------------------------------
// Tensor-core GEMM (bf16x3 fp32 emulation) + fused attention logits.
// g_h[M,128] = A[M,256] * W, block tile 128x128, k16 stages double-buffered.
// 8 warps as 2x4: warp tile 64x32; warp's 32 cols == one head.
// ---------------------------------------------------------------------------
__global__ void __launch_bounds__(256, 1)
gemm_tc(const float* __restrict__ Ain, const float* __restrict__ w,
        const float* __restrict__ att, int M) {
    // hi/lo smem: A rows stride 24 bf16 (48B = 3 x16B -> ldmatrix conflict-free)
    //             B rows stride 136 bf16 (272B = 17 x16B -> conflict-free)
    __shared__ __align__(16) __nv_bfloat16 sA[2][2][128][24]; // [buf][hi/lo][m][k]
    __shared__ __align__(16) __nv_bfloat16 sB[2][2][16][136]; // [buf][hi/lo][k][n]

    const int t = threadIdx.x;
    const int blockRow = blockIdx.x * 128;
    const int warp = t >> 5, lane = t & 31;
    const int wm = warp >> 2, wn = warp & 3;     // wn == head
    const int rquad = lane & 15, chalf = lane >> 4;
    const int grp = lane >> 2, qd = lane & 3;

    float acc[4][2][2][4];
    #pragma unroll
    for (int mt = 0; mt < 4; mt++)
        #pragma unroll
        for (int g = 0; g < 2; g++)
            #pragma unroll
            for (int s = 0; s < 2; s++)
                #pragma unroll
                for (int i = 0; i < 4; i++) acc[mt][g][s][i] = 0.f;

    // Staging decomposition
    const int am = t >> 1, akq = (t & 1) * 8;        // A: row, k-offset(0/8)
    const int bk = t >> 4, bnq = (t & 15) * 8;       // B: k-row, n-offset
    const int agr = blockRow + am;
    const float* aBase = Ain + (long long)agr * KDIM + akq;

    auto stage = [&](int kc, int buf) {
        int kbase = kc * 16;
        // ---- A ----
        float4 f0 = make_float4(0.f, 0.f, 0.f, 0.f), f1 = f0;
        if (agr < M) {
            f0 = *(const float4*)(aBase + kbase);
            f1 = *(const float4*)(aBase + kbase + 4);
        }
        float l0, l1, l2, l3, l4, l5, l6, l7;
        uint4 hi4, lo4;
        hi4.x = pack2(f0.x, f0.y, l0, l1);
        hi4.y = pack2(f0.z, f0.w, l2, l3);
        hi4.z = pack2(f1.x, f1.y, l4, l5);
        hi4.w = pack2(f1.z, f1.w, l6, l7);
        lo4.x = pack2lo(l0, l1); lo4.y = pack2lo(l2, l3);
        lo4.z = pack2lo(l4, l5); lo4.w = pack2lo(l6, l7);
        *(uint4*)&sA[buf][0][am][akq] = hi4;
        *(uint4*)&sA[buf][1][am][akq] = lo4;
        // ---- B ---- B[k][n] = w[n/32][kbase+bk][n%32]
        int kg = kbase + bk;
        const float4 b0 = *(const float4*)(w + (bnq >> 5) * (KDIM * C) + kg * C + (bnq & 31));
        const float4 b1 = *(const float4*)(w + ((bnq + 4) >> 5) * (KDIM * C) + kg * C + ((bnq + 4) & 31));
        hi4.x = pack2(b0.x, b0.y, l0, l1);
        hi4.y = pack2(b0.z, b0.w, l2, l3);
        hi4.z = pack2(b1.x, b1.y, l4, l5);
        hi4.w = pack2(b1.z, b1.w, l6, l7);
        lo4.x = pack2lo(l0, l1); lo4.y = pack2lo(l2, l3);
        lo4.z = pack2lo(l4, l5); lo4.w = pack2lo(l6, l7);
        *(uint4*)&sB[buf][0][bk][bnq] = hi4;
        *(uint4*)&sB[buf][1][bk][bnq] = lo4;
    };

    stage(0, 0);
    __syncthreads();

    // ldmatrix base addresses (per hi/lo, per buffer)
    uint32_t uA[2][2], uB[2][2];
    #pragma unroll
    for (int b = 0; b < 2; b++)
        #pragma unroll
        for (int p = 0; p < 2; p++) {
            uA[b][p] = s2u(&sA[b][p][0][0]);
            uB[b][p] = s2u(&sB[b][p][0][0]);
        }
    // A tile addr (mt): row = wm*64 + mt*16 + rquad, col-half = chalf*8
    // B tile addr (g):  row = rquad, col = wn*32 + g*16 + chalf*8
    uint32_t aOff = ((wm * 64 + rquad) * 24 + chalf * 8) * 2;
    uint32_t bOff = (rquad * 136 + wn * 32 + chalf * 8) * 2;

    for (int kc = 0; kc < 16; kc++) {
        int buf = kc & 1;
        if (kc + 1 < 16) stage(kc + 1, buf ^ 1);

        uint32_t ah[4][4], al[4][4], bh[2][4], bl[2][4];
        #pragma unroll
        for (int mt = 0; mt < 4; mt++) {
            LDSM4(ah[mt], uA[buf][0] + aOff + mt * 16 * 24 * 2);
            LDSM4(al[mt], uA[buf][1] + aOff + mt * 16 * 24 * 2);
        }
        #pragma unroll
        for (int g = 0; g < 2; g++) {
            LDSM4T(bh[g], uB[buf][0] + bOff + g * 16 * 2);
            LDSM4T(bl[g], uB[buf][1] + bOff + g * 16 * 2);
        }
        #pragma unroll
        for (int mt = 0; mt < 4; mt++)
            #pragma unroll
            for (int g = 0; g < 2; g++)
                #pragma unroll
                for (int s = 0; s < 2; s++) {
                    float* c = acc[mt][g][s];
                    MMA_BF16(c, ah[mt], bh[g][s * 2], bh[g][s * 2 + 1]); // hi*hi
                    MMA_BF16(c, al[mt], bh[g][s * 2], bh[g][s * 2 + 1]); // lo*hi
                    MMA_BF16(c, ah[mt], bl[g][s * 2], bl[g][s * 2 + 1]); // hi*lo
                }
        __syncthreads();
    }

    // ---- Epilogue: store h + fused logits ----
    // acc[mt][g][s]: rows r0 = blockRow + wm*64 + mt*16 + grp (c0,c1),
    //                r1 = r0 + 8 (c2,c3); cols = wn*32 + g*16 + s*8 + qd*2.
    float attS[2][2][2], attD[2][2][2];
    #pragma unroll
    for (int g = 0; g < 2; g++)
        #pragma unroll
        for (int s = 0; s < 2; s++)
            #pragma unroll
            for (int i = 0; i < 2; i++) {
                int cl = g * 16 + s * 8 + qd * 2 + i;
                attS[g][s][i] = __ldg(att + wn * (2 * C) + cl);
                attD[g][s][i] = __ldg(att + wn * (2 * C) + C + cl);
            }

    #pragma unroll
    for (int mt = 0; mt < 4; mt++) {
        int r0 = blockRow + wm * 64 + mt * 16 + grp;
        int r1 = r0 + 8;
        float s1a = 0.f, s1b = 0.f, s2a = 0.f, s2b = 0.f;
        #pragma unroll
        for (int g = 0; g < 2; g++)
            #pragma unroll
            for (int s = 0; s < 2; s++) {
                const float* c = acc[mt][g][s];
                int col = wn * 32 + g * 16 + s * 8 + qd * 2;
                if (r0 < M) *(float2*)(g_h + r0 * HC + col) = make_float2(c[0], c[1]);
                if (r1 < M) *(float2*)(g_h + r1 * HC + col) = make_float2(c[2], c[3]);
                s1a = fmaf(c[0], attS[g][s][0], fmaf(c[1], attS[g][s][1], s1a));
                s1b = fmaf(c[2], attS[g][s][0], fmaf(c[3], attS[g][s][1], s1b));
                s2a = fmaf(c[0], attD[g][s][0], fmaf(c[1], attD[g][s][1], s2a));
                s2b = fmaf(c[2], attD[g][s][0], fmaf(c[3], attD[g][s][1], s2b));
            }
        s1a += __shfl_xor_sync(0xffffffffu, s1a, 1);
        s1a += __shfl_xor_sync(0xffffffffu, s1a, 2);
        s1b += __shfl_xor_sync(0xffffffffu, s1b, 1);
        s1b += __shfl_xor_sync(0xffffffffu, s1b, 2);
        s2a += __shfl_xor_sync(0xffffffffu, s2a, 1);
        s2a += __shfl_xor_sync(0xffffffffu, s2a, 2);
        s2b += __shfl_xor_sync(0xffffffffu, s2b, 1);
        s2b += __shfl_xor_sync(0xffffffffu, s2b, 2);
        if (qd == 0) {
            if (r0 < M) { g_asrc[r0 * H + wn] = s1a; g_adst[r0 * H + wn] = s2a; }
            if (r1 < M) { g_asrc[r1 * H + wn] = s1b; g_adst[r1 * H + wn] = s2b; }
        }
    }
}

// ---------------------------------------------------------------------------
// Histogram: in-degree per dst + per-edge rank within its dst.
// ---------------------------------------------------------------------------
__global__ void hist_kernel(const int* __restrict__ ei, int e_cnt) {
    int e = blockIdx.x * blockDim.x + threadIdx.x;
    if (e < e_cnt) {
        int d = ei[e_cnt + e];
        g_rank[e] = atomicAdd(&g_cnt[d], 1);
    }
}

// ---------------------------------------------------------------------------
// Exclusive scan of g_cnt -> g_offs (single block, 1024 threads, chunked).
// ---------------------------------------------------------------------------
__global__ void scan_kernel(int n) {
    __shared__ int sh[1024];
    int t = threadIdx.x;
    int chunk = (n + 1023) / 1024;
    int start = t * chunk;
    int stop = min(start + chunk, n);
    int s = 0;
    for (int i = start; i < stop; i++) s += g_cnt[i];
    sh[t] = s;
    __syncthreads();
    for (int off = 1; off < 1024; off <<= 1) {
        int v = (t >= off) ? sh[t - off] : 0;
        __syncthreads();
        sh[t] += v;
        __syncthreads();
    }
    int run = (t > 0) ? sh[t - 1] : 0;
    for (int i = start; i < stop; i++) {
        g_offs[i] = run;
        run += g_cnt[i];
    }
}

// ---------------------------------------------------------------------------
// Fused edge pass: exp(LeakyReLU(a_src[s]+a_dst[d])) for 4 heads, written
// directly into CSR slot order along with the src id.
// (Max subtraction dropped: softmax is shift-invariant; logits are O(1).)
// ---------------------------------------------------------------------------
__global__ void edge12(const int* __restrict__ ei, int e_cnt) {
    int e = blockIdx.x * blockDim.x + threadIdx.x;
    if (e >= e_cnt) return;
    int s = ei[e], d = ei[e_cnt + e];
    int slot = g_offs[d] + g_rank[e];
    float4 as = *(const float4*)&g_asrc[s * 4];
    float4 ad = *(const float4*)&g_adst[d * 4];
    float a0 = as.x + ad.x, a1 = as.y + ad.y, a2 = as.z + ad.z, a3 = as.w + ad.w;
    a0 = a0 > 0.f ? a0 : 0.2f * a0;
    a1 = a1 > 0.f ? a1 : 0.2f * a1;
    a2 = a2 > 0.f ? a2 : 0.2f * a2;
    a3 = a3 > 0.f ? a3 : 0.2f * a3;
    *(float4*)&g_alpha[slot * 4] =
        make_float4(__expf(a0), __expf(a1), __expf(a2), __expf(a3));
    g_psrc[slot] = s;
}

// ---------------------------------------------------------------------------
// Gather aggregation: one warp per dst node, unrolled x4 for MLP.
// out[d] = (sum_e h[src_e]*alpha_e) / (sum_e alpha_e + eps) + bias
// ---------------------------------------------------------------------------
__global__ void agg_kernel(float* __restrict__ out, const float* __restrict__ bias, int n) {
    int gid = blockIdx.x * blockDim.x + threadIdx.x;
    int node = gid >> 5;
    if (node >= n) return;
    int lane = gid & 31;
    int hh = lane >> 3;
    int beg = g_offs[node];
    int end = beg + g_cnt[node];
    float4 acc = make_float4(0.f, 0.f, 0.f, 0.f);
    float asum = 0.f;
    int i = beg;
    for (; i + 4 <= end; i += 4) {
        int s0 = __ldg(&g_psrc[i]);
        int s1 = __ldg(&g_psrc[i + 1]);
        int s2 = __ldg(&g_psrc[i + 2]);
        int s3 = __ldg(&g_psrc[i + 3]);
        float a0 = __ldg(&g_alpha[i * 4 + hh]);
        float a1 = __ldg(&g_alpha[(i + 1) * 4 + hh]);
        float a2 = __ldg(&g_alpha[(i + 2) * 4 + hh]);
        float a3 = __ldg(&g_alpha[(i + 3) * 4 + hh]);
        float4 h0 = *(const float4*)(g_h + s0 * HC + lane * 4);
        float4 h1 = *(const float4*)(g_h + s1 * HC + lane * 4);
        float4 h2 = *(const float4*)(g_h + s2 * HC + lane * 4);
        float4 h3 = *(const float4*)(g_h + s3 * HC + lane * 4);
        asum += (a0 + a1) + (a2 + a3);
        acc.x = fmaf(h0.x, a0, acc.x); acc.y = fmaf(h0.y, a0, acc.y);
        acc.z = fmaf(h0.z, a0, acc.z); acc.w = fmaf(h0.w, a0, acc.w);
        acc.x = fmaf(h1.x, a1, acc.x); acc.y = fmaf(h1.y, a1, acc.y);
        acc.z = fmaf(h1.z, a1, acc.z); acc.w = fmaf(h1.w, a1, acc.w);
        acc.x = fmaf(h2.x, a2, acc.x); acc.y = fmaf(h2.y, a2, acc.y);
        acc.z = fmaf(h2.z, a2, acc.z); acc.w = fmaf(h2.w, a2, acc.w);
        acc.x = fmaf(h3.x, a3, acc.x); acc.y = fmaf(h3.y, a3, acc.y);
        acc.z = fmaf(h3.z, a3, acc.z); acc.w = fmaf(h3.w, a3, acc.w);
    }
    for (; i < end; i++) {
        int s = __ldg(&g_psrc[i]);
        float a = __ldg(&g_alpha[i * 4 + hh]);
        asum += a;
        float4 hv = *(const float4*)(g_h + s * HC + lane * 4);
        acc.x = fmaf(hv.x, a, acc.x);
        acc.y = fmaf(hv.y, a, acc.y);
        acc.z = fmaf(hv.z, a, acc.z);
        acc.w = fmaf(hv.w, a, acc.w);
    }
    float r = __frcp_rn(asum + 1e-16f);
    const float4 bv = *(const float4*)(bias + lane * 4);
    float4 o = make_float4(fmaf(acc.x, r, bv.x), fmaf(acc.y, r, bv.y),
                           fmaf(acc.z, r, bv.z), fmaf(acc.w, r, bv.w));
    *(float4*)(out + node * HC + lane * 4) = o;
}

// ---------------------------------------------------------------------------
extern "C" void kernel_launch(void* const* d_in, const int* in_sizes, int n_in,
                              void* d_out, int out_size) {
    const float* x    = (const float*)d_in[0];
    const int*   ei   = (const int*)d_in[1];
    const float* w    = (const float*)d_in[2];
    const float* att  = (const float*)d_in[3];
    const float* bias = (const float*)d_in[4];
    float* out = (float*)d_out;

    int n     = in_sizes[0] / KDIM;   // 50000
    int e_cnt = in_sizes[1] / 2;      // 800000

    void* cnt_ptr = nullptr;
    cudaGetSymbolAddress(&cnt_ptr, g_cnt);
    cudaMemsetAsync(cnt_ptr, 0, NMAX * sizeof(int));

    hist_kernel<<<(e_cnt + 255) / 256, 256>>>(ei, e_cnt);
    gemm_tc<<<(n + 127) / 128, 256>>>(x, w, att, n);
    scan_kernel<<<1, 1024>>>(n);
    edge12<<<(e_cnt + 255) / 256, 256>>>(ei, e_cnt);
    agg_kernel<<<(n * 32 + 255) / 256, 256>>>(out, bias, n);
}

// round 7
// speedup vs baseline: 1.8849x; 1.1714x over previous
#include <cuda_runtime.h>
#include <cuda_bf16.h>
#include <cstdint>

#define NMAX 50000
#define EMAX 800000
#define KDIM 256
#define HC   128
#define H    4
#define C    32

// Static scratch (no allocations allowed in kernel_launch).
__device__ __align__(16) float g_h[NMAX * HC];    // projected features [N][H*C]
__device__ __align__(16) float g_asrc[NMAX * H];
__device__ __align__(16) float g_adst[NMAX * H];
__device__ __align__(16) float g_alpha[EMAX * H]; // exp(alpha), CSR slot order
__device__ __align__(16) __nv_bfloat16 g_Bhi[KDIM * HC]; // pre-split weights
__device__ __align__(16) __nv_bfloat16 g_Blo[KDIM * HC];
__device__ int g_cnt[NMAX];                       // in-degree (after hist)
__device__ int g_offs[NMAX];                      // CSR offsets (exclusive scan)
__device__ int g_rank[EMAX];                      // edge rank within its dst
__device__ int g_psrc[EMAX];                      // src node id, CSR slot order

// ---------------------------------------------------------------------------
// PTX helpers
// ---------------------------------------------------------------------------
__device__ __forceinline__ uint32_t s2u(const void* p) {
    uint32_t a;
    asm("{ .reg .u64 t; cvta.to.shared.u64 t, %1; cvt.u32.u64 %0, t; }"
        : "=r"(a) : "l"(p));
    return a;
}

#define LDSM4(r, addr)                                                        \
    asm volatile("ldmatrix.sync.aligned.m8n8.x4.shared.b16 {%0,%1,%2,%3}, [%4];" \
                 : "=r"((r)[0]), "=r"((r)[1]), "=r"((r)[2]), "=r"((r)[3])     \
                 : "r"(addr))

#define LDSM4T(r, addr)                                                       \
    asm volatile("ldmatrix.sync.aligned.m8n8.x4.trans.shared.b16 {%0,%1,%2,%3}, [%4];" \
                 : "=r"((r)[0]), "=r"((r)[1]), "=r"((r)[2]), "=r"((r)[3])     \
                 : "r"(addr))

#define MMA_BF16(c, a, b0, b1)                                                \
    asm volatile("mma.sync.aligned.m16n8k16.row.col.f32.bf16.bf16.f32 "       \
                 "{%0,%1,%2,%3}, {%4,%5,%6,%7}, {%8,%9}, {%0,%1,%2,%3};"      \
                 : "+f"((c)[0]), "+f"((c)[1]), "+f"((c)[2]), "+f"((c)[3])     \
                 : "r"((a)[0]), "r"((a)[1]), "r"((a)[2]), "r"((a)[3]),        \
                   "r"(b0), "r"(b1))

// Split pair (a,b) -> packed bf16x2 hi (lo16=a, hi16=b) and packed lo residue.
// hi-as-f32 reconstructed by shl/and (bf16->f32 is a 16-bit left shift).
__device__ __forceinline__ void split2(float a, float b, uint32_t& hi, uint32_t& lo) {
    asm("cvt.rn.bf16x2.f32 %0, %1, %2;" : "=r"(hi) : "f"(b), "f"(a));
    float ahf = __uint_as_float(hi << 16);
    float bhf = __uint_as_float(hi & 0xFFFF0000u);
    float la = a - ahf, lb = b - bhf;
    asm("cvt.rn.bf16x2.f32 %0, %1, %2;" : "=r"(lo) : "f"(lb), "f"(la));
}

// ---------------------------------------------------------------------------
// Pre-split weights: B[k][n] = w[n/32][k][n%32] -> bf16 hi/lo planes.
// ---------------------------------------------------------------------------
__global__ void w2bf(const float* __restrict__ w) {
    int idx = blockIdx.x * blockDim.x + threadIdx.x;  // over KDIM*HC/2 pairs
    if (idx < KDIM * HC / 2) {
        int k = (idx * 2) / HC;
        int nn = (idx * 2) % HC;
        float a = w[(nn >> 5) * (KDIM * C) + k * C + (nn & 31)];
        float b = w[((nn + 1) >> 5) * (KDIM * C) + k * C + ((nn + 1) & 31)];
        uint32_t hi, lo;
        split2(a, b, hi, lo);
        *(uint32_t*)&g_Bhi[idx * 2] = hi;
        *(uint32_t*)&g_Blo[idx * 2] = lo;
    }
}

// ---------------------------------------------------------------------------
// Block-specialized phase:
//  blocks [0,nGemm): tensor-core GEMM (bf16x3 fp32 emulation) + fused logits.
//  blocks [nGemm,..): in-degree histogram (rides the gemm tail).
// ---------------------------------------------------------------------------
__global__ void __launch_bounds__(256, 2)
gemm_tc(const float* __restrict__ Ain, const float* __restrict__ att,
        const int* __restrict__ ei, int M, int e_cnt, int nGemm) {
    __shared__ __align__(16) __nv_bfloat16 sA[2][2][128][24]; // [buf][hi/lo][m][k]
    __shared__ __align__(16) __nv_bfloat16 sB[2][2][16][136]; // [buf][hi/lo][k][n]

    if (blockIdx.x >= nGemm) {
        int e = (blockIdx.x - nGemm) * blockDim.x + threadIdx.x;
        if (e < e_cnt) {
            int d = ei[e_cnt + e];
            g_rank[e] = atomicAdd(&g_cnt[d], 1);
        }
        return;
    }

    const int t = threadIdx.x;
    const int blockRow = blockIdx.x * 128;
    const int warp = t >> 5, lane = t & 31;
    const int wm = warp >> 2, wn = warp & 3;     // wn == head
    const int rquad = lane & 15, chalf = lane >> 4;
    const int grp = lane >> 2, qd = lane & 3;

    float acc[4][2][2][4];
    #pragma unroll
    for (int mt = 0; mt < 4; mt++)
        #pragma unroll
        for (int g = 0; g < 2; g++)
            #pragma unroll
            for (int s = 0; s < 2; s++)
                #pragma unroll
                for (int i = 0; i < 4; i++) acc[mt][g][s][i] = 0.f;

    // Staging decomposition
    const int am = t >> 1, akq = (t & 1) * 8;        // A: row, k-offset(0/8)
    const int bk = t >> 4, bnq = (t & 15) * 8;       // B: k-row, n-offset
    const int agr = blockRow + am;
    const float* aBase = Ain + (long long)agr * KDIM + akq;

    auto stage = [&](int kc, int buf) {
        int kbase = kc * 16;
        // ---- A: load f32, split to hi/lo bf16 ----
        float4 f0 = make_float4(0.f, 0.f, 0.f, 0.f), f1 = f0;
        if (agr < M) {
            f0 = *(const float4*)(aBase + kbase);
            f1 = *(const float4*)(aBase + kbase + 4);
        }
        uint4 hi4, lo4;
        split2(f0.x, f0.y, hi4.x, lo4.x);
        split2(f0.z, f0.w, hi4.y, lo4.y);
        split2(f1.x, f1.y, hi4.z, lo4.z);
        split2(f1.z, f1.w, hi4.w, lo4.w);
        *(uint4*)&sA[buf][0][am][akq] = hi4;
        *(uint4*)&sA[buf][1][am][akq] = lo4;
        // ---- B: straight copies from pre-split planes ----
        int kg = kbase + bk;
        *(uint4*)&sB[buf][0][bk][bnq] = *(const uint4*)&g_Bhi[kg * HC + bnq];
        *(uint4*)&sB[buf][1][bk][bnq] = *(const uint4*)&g_Blo[kg * HC + bnq];
    };

    stage(0, 0);
    __syncthreads();

    uint32_t uA[2][2], uB[2][2];
    #pragma unroll
    for (int b = 0; b < 2; b++)
        #pragma unroll
        for (int p = 0; p < 2; p++) {
            uA[b][p] = s2u(&sA[b][p][0][0]);
            uB[b][p] = s2u(&sB[b][p][0][0]);
        }
    uint32_t aOff = ((wm * 64 + rquad) * 24 + chalf * 8) * 2;
    uint32_t bOff = (rquad * 136 + wn * 32 + chalf * 8) * 2;

    for (int kc = 0; kc < 16; kc++) {
        int buf = kc & 1;
        if (kc + 1 < 16) stage(kc + 1, buf ^ 1);

        uint32_t ah[4][4], al[4][4], bh[2][4], bl[2][4];
        #pragma unroll
        for (int mt = 0; mt < 4; mt++) {
            LDSM4(ah[mt], uA[buf][0] + aOff + mt * 16 * 24 * 2);
            LDSM4(al[mt], uA[buf][1] + aOff + mt * 16 * 24 * 2);
        }
        #pragma unroll
        for (int g = 0; g < 2; g++) {
            LDSM4T(bh[g], uB[buf][0] + bOff + g * 16 * 2);
            LDSM4T(bl[g], uB[buf][1] + bOff + g * 16 * 2);
        }
        #pragma unroll
        for (int mt = 0; mt < 4; mt++)
            #pragma unroll
            for (int g = 0; g < 2; g++)
                #pragma unroll
                for (int s = 0; s < 2; s++) {
                    float* c = acc[mt][g][s];
                    MMA_BF16(c, ah[mt], bh[g][s * 2], bh[g][s * 2 + 1]); // hi*hi
                    MMA_BF16(c, al[mt], bh[g][s * 2], bh[g][s * 2 + 1]); // lo*hi
                    MMA_BF16(c, ah[mt], bl[g][s * 2], bl[g][s * 2 + 1]); // hi*lo
                }
        __syncthreads();
    }

    // ---- Epilogue: store h + fused logits ----
    float attS[2][2][2], attD[2][2][2];
    #pragma unroll
    for (int g = 0; g < 2; g++)
        #pragma unroll
        for (int s = 0; s < 2; s++)
            #pragma unroll
            for (int i = 0; i < 2; i++) {
                int cl = g * 16 + s * 8 + qd * 2 + i;
                attS[g][s][i] = __ldg(att + wn * (2 * C) + cl);
                attD[g][s][i] = __ldg(att + wn * (2 * C) + C + cl);
            }

    #pragma unroll
    for (int mt = 0; mt < 4; mt++) {
        int r0 = blockRow + wm * 64 + mt * 16 + grp;
        int r1 = r0 + 8;
        float s1a = 0.f, s1b = 0.f, s2a = 0.f, s2b = 0.f;
        #pragma unroll
        for (int g = 0; g < 2; g++)
            #pragma unroll
            for (int s = 0; s < 2; s++) {
                const float* c = acc[mt][g][s];
                int col = wn * 32 + g * 16 + s * 8 + qd * 2;
                if (r0 < M) *(float2*)(g_h + r0 * HC + col) = make_float2(c[0], c[1]);
                if (r1 < M) *(float2*)(g_h + r1 * HC + col) = make_float2(c[2], c[3]);
                s1a = fmaf(c[0], attS[g][s][0], fmaf(c[1], attS[g][s][1], s1a));
                s1b = fmaf(c[2], attS[g][s][0], fmaf(c[3], attS[g][s][1], s1b));
                s2a = fmaf(c[0], attD[g][s][0], fmaf(c[1], attD[g][s][1], s2a));
                s2b = fmaf(c[2], attD[g][s][0], fmaf(c[3], attD[g][s][1], s2b));
            }
        s1a += __shfl_xor_sync(0xffffffffu, s1a, 1);
        s1a += __shfl_xor_sync(0xffffffffu, s1a, 2);
        s1b += __shfl_xor_sync(0xffffffffu, s1b, 1);
        s1b += __shfl_xor_sync(0xffffffffu, s1b, 2);
        s2a += __shfl_xor_sync(0xffffffffu, s2a, 1);
        s2a += __shfl_xor_sync(0xffffffffu, s2a, 2);
        s2b += __shfl_xor_sync(0xffffffffu, s2b, 1);
        s2b += __shfl_xor_sync(0xffffffffu, s2b, 2);
        if (qd == 0) {
            if (r0 < M) { g_asrc[r0 * H + wn] = s1a; g_adst[r0 * H + wn] = s2a; }
            if (r1 < M) { g_asrc[r1 * H + wn] = s1b; g_adst[r1 * H + wn] = s2b; }
        }
    }
}

// ---------------------------------------------------------------------------
// Exclusive scan of g_cnt -> g_offs (single block, 1024 threads, chunked).
// ---------------------------------------------------------------------------
__global__ void scan_kernel(int n) {
    __shared__ int sh[1024];
    int t = threadIdx.x;
    int chunk = (n + 1023) / 1024;
    int start = t * chunk;
    int stop = min(start + chunk, n);
    int s = 0;
    for (int i = start; i < stop; i++) s += g_cnt[i];
    sh[t] = s;
    __syncthreads();
    for (int off = 1; off < 1024; off <<= 1) {
        int v = (t >= off) ? sh[t - off] : 0;
        __syncthreads();
        sh[t] += v;
        __syncthreads();
    }
    int run = (t > 0) ? sh[t - 1] : 0;
    for (int i = start; i < stop; i++) {
        g_offs[i] = run;
        run += g_cnt[i];
    }
}

// ---------------------------------------------------------------------------
// Fused edge pass: exp(LeakyReLU(a_src[s]+a_dst[d])) for 4 heads, written
// directly into CSR slot order along with the src id.
// (Max subtraction dropped: softmax is shift-invariant; logits are O(1).)
// ---------------------------------------------------------------------------
__global__ void edge12(const int* __restrict__ ei, int e_cnt) {
    int e = blockIdx.x * blockDim.x + threadIdx.x;
    if (e >= e_cnt) return;
    int s = ei[e], d = ei[e_cnt + e];
    int slot = g_offs[d] + g_rank[e];
    float4 as = *(const float4*)&g_asrc[s * 4];
    float4 ad = *(const float4*)&g_adst[d * 4];
    float a0 = as.x + ad.x, a1 = as.y + ad.y, a2 = as.z + ad.z, a3 = as.w + ad.w;
    a0 = a0 > 0.f ? a0 : 0.2f * a0;
    a1 = a1 > 0.f ? a1 : 0.2f * a1;
    a2 = a2 > 0.f ? a2 : 0.2f * a2;
    a3 = a3 > 0.f ? a3 : 0.2f * a3;
    *(float4*)&g_alpha[slot * 4] =
        make_float4(__expf(a0), __expf(a1), __expf(a2), __expf(a3));
    g_psrc[slot] = s;
}

// ---------------------------------------------------------------------------
// Gather aggregation: one warp per dst node, unrolled x4 for MLP.
// out[d] = (sum_e h[src_e]*alpha_e) / (sum_e alpha_e + eps) + bias
// ---------------------------------------------------------------------------
__global__ void agg_kernel(float* __restrict__ out, const float* __restrict__ bias, int n) {
    int gid = blockIdx.x * blockDim.x + threadIdx.x;
    int node = gid >> 5;
    if (node >= n) return;
    int lane = gid & 31;
    int hh = lane >> 3;
    int beg = g_offs[node];
    int end = beg + g_cnt[node];
    float4 acc = make_float4(0.f, 0.f, 0.f, 0.f);
    float asum = 0.f;
    int i = beg;
    for (; i + 4 <= end; i += 4) {
        int s0 = __ldg(&g_psrc[i]);
        int s1 = __ldg(&g_psrc[i + 1]);
        int s2 = __ldg(&g_psrc[i + 2]);
        int s3 = __ldg(&g_psrc[i + 3]);
        float a0 = __ldg(&g_alpha[i * 4 + hh]);
        float a1 = __ldg(&g_alpha[(i + 1) * 4 + hh]);
        float a2 = __ldg(&g_alpha[(i + 2) * 4 + hh]);
        float a3 = __ldg(&g_alpha[(i + 3) * 4 + hh]);
        float4 h0 = *(const float4*)(g_h + s0 * HC + lane * 4);
        float4 h1 = *(const float4*)(g_h + s1 * HC + lane * 4);
        float4 h2 = *(const float4*)(g_h + s2 * HC + lane * 4);
        float4 h3 = *(const float4*)(g_h + s3 * HC + lane * 4);
        asum += (a0 + a1) + (a2 + a3);
        acc.x = fmaf(h0.x, a0, acc.x); acc.y = fmaf(h0.y, a0, acc.y);
        acc.z = fmaf(h0.z, a0, acc.z); acc.w = fmaf(h0.w, a0, acc.w);
        acc.x = fmaf(h1.x, a1, acc.x); acc.y = fmaf(h1.y, a1, acc.y);
        acc.z = fmaf(h1.z, a1, acc.z); acc.w = fmaf(h1.w, a1, acc.w);
        acc.x = fmaf(h2.x, a2, acc.x); acc.y = fmaf(h2.y, a2, acc.y);
        acc.z = fmaf(h2.z, a2, acc.z); acc.w = fmaf(h2.w, a2, acc.w);
        acc.x = fmaf(h3.x, a3, acc.x); acc.y = fmaf(h3.y, a3, acc.y);
        acc.z = fmaf(h3.z, a3, acc.z); acc.w = fmaf(h3.w, a3, acc.w);
    }
    for (; i < end; i++) {
        int s = __ldg(&g_psrc[i]);
        float a = __ldg(&g_alpha[i * 4 + hh]);
        asum += a;
        float4 hv = *(const float4*)(g_h + s * HC + lane * 4);
        acc.x = fmaf(hv.x, a, acc.x);
        acc.y = fmaf(hv.y, a, acc.y);
        acc.z = fmaf(hv.z, a, acc.z);
        acc.w = fmaf(hv.w, a, acc.w);
    }
    float r = __frcp_rn(asum + 1e-16f);
    const float4 bv = *(const float4*)(bias + lane * 4);
    float4 o = make_float4(fmaf(acc.x, r, bv.x), fmaf(acc.y, r, bv.y),
                           fmaf(acc.z, r, bv.z), fmaf(acc.w, r, bv.w));
    *(float4*)(out + node * HC + lane * 4) = o;
}

// ---------------------------------------------------------------------------
extern "C" void kernel_launch(void* const* d_in, const int* in_sizes, int n_in,
                              void* d_out, int out_size) {
    const float* x    = (const float*)d_in[0];
    const int*   ei   = (const int*)d_in[1];
    const float* w    = (const float*)d_in[2];
    const float* att  = (const float*)d_in[3];
    const float* bias = (const float*)d_in[4];
    float* out = (float*)d_out;

    int n     = in_sizes[0] / KDIM;   // 50000
    int e_cnt = in_sizes[1] / 2;      // 800000

    void* cnt_ptr = nullptr;
    cudaGetSymbolAddress(&cnt_ptr, g_cnt);
    cudaMemsetAsync(cnt_ptr, 0, NMAX * sizeof(int));

    w2bf<<<(KDIM * HC / 2 + 255) / 256, 256>>>(w);
    int nGemm = (n + 127) / 128;
    int nHist = (e_cnt + 255) / 256;
    gemm_tc<<<nGemm + nHist, 256>>>(x, att, ei, n, e_cnt, nGemm);
    scan_kernel<<<1, 1024>>>(n);
    edge12<<<(e_cnt + 255) / 256, 256>>>(ei, e_cnt);
    agg_kernel<<<(n * 32 + 255) / 256, 256>>>(out, bias, n);
}

// round 8
// speedup vs baseline: 2.8024x; 1.4867x over previous
#include <cuda_runtime.h>
#include <cuda_bf16.h>
#include <cstdint>

#define NMAX 50000
#define EMAX 800000
#define KDIM 256
#define HC   128
#define H    4
#define C    32

// Static scratch (no allocations allowed in kernel_launch).
__device__ __align__(16) float g_h[NMAX * HC];    // projected features [N][H*C]
__device__ __align__(16) float g_asrc[NMAX * H];
// Packed per-node record: [0:4)=adst(4 heads), [4]=local offs (int), [5]=cnt (int), [6:8) pad
__device__ __align__(32) float g_nodeD[NMAX * 8];
__device__ __align__(16) float g_alpha[EMAX * H]; // exp(alpha), CSR slot order
__device__ __align__(16) __nv_bfloat16 g_Bhi[KDIM * HC]; // pre-split weights
__device__ __align__(16) __nv_bfloat16 g_Blo[KDIM * HC];
__device__ int g_cnt[NMAX];                       // in-degree (after hist)
__device__ int g_rank[EMAX];                      // edge rank within its dst
__device__ int g_psrc[EMAX];                      // src node id, CSR slot order
__device__ int g_bsum[64];                        // scanA per-block totals
__device__ int g_boff[64];                        // exclusive scan of block totals

// ---------------------------------------------------------------------------
// PTX helpers
// ---------------------------------------------------------------------------
__device__ __forceinline__ uint32_t s2u(const void* p) {
    uint32_t a;
    asm("{ .reg .u64 t; cvta.to.shared.u64 t, %1; cvt.u32.u64 %0, t; }"
        : "=r"(a) : "l"(p));
    return a;
}

#define LDSM4(r, addr)                                                        \
    asm volatile("ldmatrix.sync.aligned.m8n8.x4.shared.b16 {%0,%1,%2,%3}, [%4];" \
                 : "=r"((r)[0]), "=r"((r)[1]), "=r"((r)[2]), "=r"((r)[3])     \
                 : "r"(addr))

#define LDSM4T(r, addr)                                                       \
    asm volatile("ldmatrix.sync.aligned.m8n8.x4.trans.shared.b16 {%0,%1,%2,%3}, [%4];" \
                 : "=r"((r)[0]), "=r"((r)[1]), "=r"((r)[2]), "=r"((r)[3])     \
                 : "r"(addr))

#define MMA_BF16(c, a, b0, b1)                                                \
    asm volatile("mma.sync.aligned.m16n8k16.row.col.f32.bf16.bf16.f32 "       \
                 "{%0,%1,%2,%3}, {%4,%5,%6,%7}, {%8,%9}, {%0,%1,%2,%3};"      \
                 : "+f"((c)[0]), "+f"((c)[1]), "+f"((c)[2]), "+f"((c)[3])     \
                 : "r"((a)[0]), "r"((a)[1]), "r"((a)[2]), "r"((a)[3]),        \
                   "r"(b0), "r"(b1))

#define CP_ASYNC16(dst, src)                                                  \
    asm volatile("cp.async.ca.shared.global [%0], [%1], 16;"                  \
                 :: "r"(dst), "l"(src))
#define CP_COMMIT()  asm volatile("cp.async.commit_group;" ::: "memory")
#define CP_WAIT0()   asm volatile("cp.async.wait_group 0;" ::: "memory")

// Split pair (a,b) -> packed bf16x2 hi (lo16=a, hi16=b) and packed lo residue.
__device__ __forceinline__ void split2(float a, float b, uint32_t& hi, uint32_t& lo) {
    asm("cvt.rn.bf16x2.f32 %0, %1, %2;" : "=r"(hi) : "f"(b), "f"(a));
    float ahf = __uint_as_float(hi << 16);
    float bhf = __uint_as_float(hi & 0xFFFF0000u);
    float la = a - ahf, lb = b - bhf;
    asm("cvt.rn.bf16x2.f32 %0, %1, %2;" : "=r"(lo) : "f"(lb), "f"(la));
}

// ---------------------------------------------------------------------------
// Pre-split weights into bf16 hi/lo planes; also zero g_cnt.
// ---------------------------------------------------------------------------
__global__ void w2bf(const float* __restrict__ w) {
    int idx = blockIdx.x * blockDim.x + threadIdx.x;
    if (idx < KDIM * HC / 2) {
        int k = (idx * 2) / HC;
        int nn = (idx * 2) % HC;
        float a = w[(nn >> 5) * (KDIM * C) + k * C + (nn & 31)];
        float b = w[((nn + 1) >> 5) * (KDIM * C) + k * C + ((nn + 1) & 31)];
        uint32_t hi, lo;
        split2(a, b, hi, lo);
        *(uint32_t*)&g_Bhi[idx * 2] = hi;
        *(uint32_t*)&g_Blo[idx * 2] = lo;
    }
    if (idx < NMAX) g_cnt[idx] = 0;
}

// ---------------------------------------------------------------------------
// Block-specialized phase:
//  blocks [0,nGemm): tensor-core GEMM (bf16x3 fp32 emulation) + fused logits.
//  blocks [nGemm,..): in-degree histogram (rides the gemm tail).
// ---------------------------------------------------------------------------
__global__ void __launch_bounds__(256, 2)
gemm_tc(const float* __restrict__ Ain, const float* __restrict__ att,
        const int* __restrict__ ei, int M, int e_cnt, int nGemm) {
    __shared__ __align__(16) __nv_bfloat16 sA[2][2][128][24]; // [buf][hi/lo][m][k]
    __shared__ __align__(16) __nv_bfloat16 sB[2][2][16][136]; // [buf][hi/lo][k][n]

    if (blockIdx.x >= nGemm) {
        int e = (blockIdx.x - nGemm) * blockDim.x + threadIdx.x;
        if (e < e_cnt) {
            int d = ei[e_cnt + e];
            g_rank[e] = atomicAdd(&g_cnt[d], 1);
        }
        return;
    }

    const int t = threadIdx.x;
    const int blockRow = blockIdx.x * 128;
    const int warp = t >> 5, lane = t & 31;
    const int wm = warp >> 2, wn = warp & 3;     // wn == head
    const int rquad = lane & 15, chalf = lane >> 4;
    const int grp = lane >> 2, qd = lane & 3;

    float acc[4][2][2][4];
    #pragma unroll
    for (int mt = 0; mt < 4; mt++)
        #pragma unroll
        for (int g = 0; g < 2; g++)
            #pragma unroll
            for (int s = 0; s < 2; s++)
                #pragma unroll
                for (int i = 0; i < 4; i++) acc[mt][g][s][i] = 0.f;

    const int am = t >> 1, akq = (t & 1) * 8;        // A: row, k-offset(0/8)
    const int bk = t >> 4, bnq = (t & 15) * 8;       // B: k-row, n-offset
    const int agr = blockRow + am;
    const float* aBase = Ain + (long long)agr * KDIM + akq;

    auto stage = [&](int kc, int buf) {
        int kbase = kc * 16;
        int kg = kbase + bk;
        // ---- B: cp.async straight from pre-split planes ----
        CP_ASYNC16(s2u(&sB[buf][0][bk][bnq]), &g_Bhi[kg * HC + bnq]);
        CP_ASYNC16(s2u(&sB[buf][1][bk][bnq]), &g_Blo[kg * HC + bnq]);
        CP_COMMIT();
        // ---- A: load f32, split to hi/lo bf16 ----
        float4 f0 = make_float4(0.f, 0.f, 0.f, 0.f), f1 = f0;
        if (agr < M) {
            f0 = *(const float4*)(aBase + kbase);
            f1 = *(const float4*)(aBase + kbase + 4);
        }
        uint4 hi4, lo4;
        split2(f0.x, f0.y, hi4.x, lo4.x);
        split2(f0.z, f0.w, hi4.y, lo4.y);
        split2(f1.x, f1.y, hi4.z, lo4.z);
        split2(f1.z, f1.w, hi4.w, lo4.w);
        *(uint4*)&sA[buf][0][am][akq] = hi4;
        *(uint4*)&sA[buf][1][am][akq] = lo4;
    };

    stage(0, 0);
    CP_WAIT0();
    __syncthreads();

    uint32_t uA[2][2], uB[2][2];
    #pragma unroll
    for (int b = 0; b < 2; b++)
        #pragma unroll
        for (int p = 0; p < 2; p++) {
            uA[b][p] = s2u(&sA[b][p][0][0]);
            uB[b][p] = s2u(&sB[b][p][0][0]);
        }
    uint32_t aOff = ((wm * 64 + rquad) * 24 + chalf * 8) * 2;
    uint32_t bOff = (rquad * 136 + wn * 32 + chalf * 8) * 2;

    for (int kc = 0; kc < 16; kc++) {
        int buf = kc & 1;
        if (kc + 1 < 16) stage(kc + 1, buf ^ 1);

        uint32_t ah[4][4], al[4][4], bh[2][4], bl[2][4];
        #pragma unroll
        for (int mt = 0; mt < 4; mt++) {
            LDSM4(ah[mt], uA[buf][0] + aOff + mt * 16 * 24 * 2);
            LDSM4(al[mt], uA[buf][1] + aOff + mt * 16 * 24 * 2);
        }
        #pragma unroll
        for (int g = 0; g < 2; g++) {
            LDSM4T(bh[g], uB[buf][0] + bOff + g * 16 * 2);
            LDSM4T(bl[g], uB[buf][1] + bOff + g * 16 * 2);
        }
        #pragma unroll
        for (int mt = 0; mt < 4; mt++)
            #pragma unroll
            for (int g = 0; g < 2; g++)
                #pragma unroll
                for (int s = 0; s < 2; s++) {
                    float* c = acc[mt][g][s];
                    MMA_BF16(c, ah[mt], bh[g][s * 2], bh[g][s * 2 + 1]); // hi*hi
                    MMA_BF16(c, al[mt], bh[g][s * 2], bh[g][s * 2 + 1]); // lo*hi
                    MMA_BF16(c, ah[mt], bl[g][s * 2], bl[g][s * 2 + 1]); // hi*lo
                }
        CP_WAIT0();
        __syncthreads();
    }

    // ---- Epilogue: store h + fused logits ----
    float attS[2][2][2], attD[2][2][2];
    #pragma unroll
    for (int g = 0; g < 2; g++)
        #pragma unroll
        for (int s = 0; s < 2; s++)
            #pragma unroll
            for (int i = 0; i < 2; i++) {
                int cl = g * 16 + s * 8 + qd * 2 + i;
                attS[g][s][i] = __ldg(att + wn * (2 * C) + cl);
                attD[g][s][i] = __ldg(att + wn * (2 * C) + C + cl);
            }

    #pragma unroll
    for (int mt = 0; mt < 4; mt++) {
        int r0 = blockRow + wm * 64 + mt * 16 + grp;
        int r1 = r0 + 8;
        float s1a = 0.f, s1b = 0.f, s2a = 0.f, s2b = 0.f;
        #pragma unroll
        for (int g = 0; g < 2; g++)
            #pragma unroll
            for (int s = 0; s < 2; s++) {
                const float* c = acc[mt][g][s];
                int col = wn * 32 + g * 16 + s * 8 + qd * 2;
                if (r0 < M) *(float2*)(g_h + r0 * HC + col) = make_float2(c[0], c[1]);
                if (r1 < M) *(float2*)(g_h + r1 * HC + col) = make_float2(c[2], c[3]);
                s1a = fmaf(c[0], attS[g][s][0], fmaf(c[1], attS[g][s][1], s1a));
                s1b = fmaf(c[2], attS[g][s][0], fmaf(c[3], attS[g][s][1], s1b));
                s2a = fmaf(c[0], attD[g][s][0], fmaf(c[1], attD[g][s][1], s2a));
                s2b = fmaf(c[2], attD[g][s][0], fmaf(c[3], attD[g][s][1], s2b));
            }
        s1a += __shfl_xor_sync(0xffffffffu, s1a, 1);
        s1a += __shfl_xor_sync(0xffffffffu, s1a, 2);
        s1b += __shfl_xor_sync(0xffffffffu, s1b, 1);
        s1b += __shfl_xor_sync(0xffffffffu, s1b, 2);
        s2a += __shfl_xor_sync(0xffffffffu, s2a, 1);
        s2a += __shfl_xor_sync(0xffffffffu, s2a, 2);
        s2b += __shfl_xor_sync(0xffffffffu, s2b, 1);
        s2b += __shfl_xor_sync(0xffffffffu, s2b, 2);
        if (qd == 0) {
            if (r0 < M) { g_asrc[r0 * H + wn] = s1a; g_nodeD[r0 * 8 + wn] = s2a; }
            if (r1 < M) { g_asrc[r1 * H + wn] = s1b; g_nodeD[r1 * 8 + wn] = s2b; }
        }
    }
}

// ---------------------------------------------------------------------------
// scanA: coalesced block-level exclusive scan of g_cnt (1024 elems/block).
// Writes local prefix + cnt into the packed node record, block total to g_bsum.
// ---------------------------------------------------------------------------
__global__ void scanA(int n) {
    __shared__ int sh[1024];
    int t = threadIdx.x;
    int i = blockIdx.x * 1024 + t;
    int v = (i < n) ? g_cnt[i] : 0;
    sh[t] = v;
    __syncthreads();
    #pragma unroll
    for (int off = 1; off < 1024; off <<= 1) {
        int u = (t >= off) ? sh[t - off] : 0;
        __syncthreads();
        sh[t] += u;
        __syncthreads();
    }
    if (i < n) {
        ((int*)g_nodeD)[i * 8 + 4] = sh[t] - v;   // local exclusive prefix
        ((int*)g_nodeD)[i * 8 + 5] = v;           // cnt
    }
    if (t == 1023) g_bsum[blockIdx.x] = sh[1023];
}

// scanB: exclusive scan of up to 64 block totals.
__global__ void scanB(int nb) {
    __shared__ int sh[64];
    int t = threadIdx.x;
    int v = (t < nb) ? g_bsum[t] : 0;
    sh[t] = v;
    __syncthreads();
    #pragma unroll
    for (int off = 1; off < 64; off <<= 1) {
        int u = (t >= off) ? sh[t - off] : 0;
        __syncthreads();
        sh[t] += u;
        __syncthreads();
    }
    g_boff[t] = sh[t] - v;
}

// ---------------------------------------------------------------------------
// Fused edge pass: exp(LeakyReLU(a_src[s]+a_dst[d])) for 4 heads, written
// directly into CSR slot order along with the src id.
// ---------------------------------------------------------------------------
__global__ void edge12(const int* __restrict__ ei, int e_cnt) {
    int e = blockIdx.x * blockDim.x + threadIdx.x;
    if (e >= e_cnt) return;
    int s = ei[e], d = ei[e_cnt + e];
    float4 as = *(const float4*)&g_asrc[s * 4];
    float4 ad = *(const float4*)&g_nodeD[d * 8];      // adst (same 32B rec as offs)
    int offsL = __ldg((const int*)g_nodeD + d * 8 + 4);
    int slot = offsL + __ldg(&g_boff[d >> 10]) + g_rank[e];
    float a0 = as.x + ad.x, a1 = as.y + ad.y, a2 = as.z + ad.z, a3 = as.w + ad.w;
    a0 = a0 > 0.f ? a0 : 0.2f * a0;
    a1 = a1 > 0.f ? a1 : 0.2f * a1;
    a2 = a2 > 0.f ? a2 : 0.2f * a2;
    a3 = a3 > 0.f ? a3 : 0.2f * a3;
    *(float4*)&g_alpha[slot * 4] =
        make_float4(__expf(a0), __expf(a1), __expf(a2), __expf(a3));
    g_psrc[slot] = s;
}

// ---------------------------------------------------------------------------
// Gather aggregation: one warp per dst node, unrolled x4 for MLP.
// out[d] = (sum_e h[src_e]*alpha_e) / (sum_e alpha_e + eps) + bias
// ---------------------------------------------------------------------------
__global__ void agg_kernel(float* __restrict__ out, const float* __restrict__ bias, int n) {
    int gid = blockIdx.x * blockDim.x + threadIdx.x;
    int node = gid >> 5;
    if (node >= n) return;
    int lane = gid & 31;
    int hh = lane >> 3;
    int beg = __ldg((const int*)g_nodeD + node * 8 + 4) + __ldg(&g_boff[node >> 10]);
    int end = beg + __ldg((const int*)g_nodeD + node * 8 + 5);
    float4 acc = make_float4(0.f, 0.f, 0.f, 0.f);
    float asum = 0.f;
    int i = beg;
    for (; i + 4 <= end; i += 4) {
        int s0 = __ldg(&g_psrc[i]);
        int s1 = __ldg(&g_psrc[i + 1]);
        int s2 = __ldg(&g_psrc[i + 2]);
        int s3 = __ldg(&g_psrc[i + 3]);
        float a0 = __ldg(&g_alpha[i * 4 + hh]);
        float a1 = __ldg(&g_alpha[(i + 1) * 4 + hh]);
        float a2 = __ldg(&g_alpha[(i + 2) * 4 + hh]);
        float a3 = __ldg(&g_alpha[(i + 3) * 4 + hh]);
        float4 h0 = *(const float4*)(g_h + s0 * HC + lane * 4);
        float4 h1 = *(const float4*)(g_h + s1 * HC + lane * 4);
        float4 h2 = *(const float4*)(g_h + s2 * HC + lane * 4);
        float4 h3 = *(const float4*)(g_h + s3 * HC + lane * 4);
        asum += (a0 + a1) + (a2 + a3);
        acc.x = fmaf(h0.x, a0, acc.x); acc.y = fmaf(h0.y, a0, acc.y);
        acc.z = fmaf(h0.z, a0, acc.z); acc.w = fmaf(h0.w, a0, acc.w);
        acc.x = fmaf(h1.x, a1, acc.x); acc.y = fmaf(h1.y, a1, acc.y);
        acc.z = fmaf(h1.z, a1, acc.z); acc.w = fmaf(h1.w, a1, acc.w);
        acc.x = fmaf(h2.x, a2, acc.x); acc.y = fmaf(h2.y, a2, acc.y);
        acc.z = fmaf(h2.z, a2, acc.z); acc.w = fmaf(h2.w, a2, acc.w);
        acc.x = fmaf(h3.x, a3, acc.x); acc.y = fmaf(h3.y, a3, acc.y);
        acc.z = fmaf(h3.z, a3, acc.z); acc.w = fmaf(h3.w, a3, acc.w);
    }
    for (; i < end; i++) {
        int s = __ldg(&g_psrc[i]);
        float a = __ldg(&g_alpha[i * 4 + hh]);
        asum += a;
        float4 hv = *(const float4*)(g_h + s * HC + lane * 4);
        acc.x = fmaf(hv.x, a, acc.x);
        acc.y = fmaf(hv.y, a, acc.y);
        acc.z = fmaf(hv.z, a, acc.z);
        acc.w = fmaf(hv.w, a, acc.w);
    }
    float r = __frcp_rn(asum + 1e-16f);
    const float4 bv = *(const float4*)(bias + lane * 4);
    float4 o = make_float4(fmaf(acc.x, r, bv.x), fmaf(acc.y, r, bv.y),
                           fmaf(acc.z, r, bv.z), fmaf(acc.w, r, bv.w));
    *(float4*)(out + node * HC + lane * 4) = o;
}

// ---------------------------------------------------------------------------
extern "C" void kernel_launch(void* const* d_in, const int* in_sizes, int n_in,
                              void* d_out, int out_size) {
    const float* x    = (const float*)d_in[0];
    const int*   ei   = (const int*)d_in[1];
    const float* w    = (const float*)d_in[2];
    const float* att  = (const float*)d_in[3];
    const float* bias = (const float*)d_in[4];
    float* out = (float*)d_out;

    int n     = in_sizes[0] / KDIM;   // 50000
    int e_cnt = in_sizes[1] / 2;      // 800000

    w2bf<<<(NMAX + 255) / 256, 256>>>(w);
    int nGemm = (n + 127) / 128;
    int nHist = (e_cnt + 255) / 256;
    gemm_tc<<<nGemm + nHist, 256>>>(x, att, ei, n, e_cnt, nGemm);
    int nB = (n + 1023) / 1024;
    scanA<<<nB, 1024>>>(n);
    scanB<<<1, 64>>>(nB);
    edge12<<<(e_cnt + 255) / 256, 256>>>(ei, e_cnt);
    agg_kernel<<<(n * 32 + 255) / 256, 256>>>(out, bias, n);
}

// round 9
// speedup vs baseline: 3.0232x; 1.0788x over previous
#include <cuda_runtime.h>
#include <cuda_bf16.h>
#include <cstdint>

#define NMAX 50000
#define EMAX 800000
#define KDIM 256
#define HC   128
#define H    4
#define C    32

// Static scratch (no allocations allowed in kernel_launch).
__device__ __align__(16) float g_h[NMAX * HC];    // projected features [N][H*C]
__device__ __align__(16) float g_asrc[NMAX * H];
// Packed per-node record: [0:4)=adst(4 heads), [4]=global offs (int), [5]=cnt (int), [6:8) pad
__device__ __align__(32) float g_nodeD[NMAX * 8];
__device__ __align__(16) __nv_bfloat16 g_Bhi[KDIM * HC]; // pre-split weights
__device__ __align__(16) __nv_bfloat16 g_Blo[KDIM * HC];
__device__ int g_cnt[NMAX];                       // in-degree (after hist)
__device__ int g_cur[NMAX];                       // CSR fill cursors
__device__ int g_psrc[EMAX];                      // src node id, CSR slot order
__device__ int g_total;                           // running block-offset counter

// ---------------------------------------------------------------------------
// PTX helpers
// ---------------------------------------------------------------------------
__device__ __forceinline__ uint32_t s2u(const void* p) {
    uint32_t a;
    asm("{ .reg .u64 t; cvta.to.shared.u64 t, %1; cvt.u32.u64 %0, t; }"
        : "=r"(a) : "l"(p));
    return a;
}

#define LDSM4(r, addr)                                                        \
    asm volatile("ldmatrix.sync.aligned.m8n8.x4.shared.b16 {%0,%1,%2,%3}, [%4];" \
                 : "=r"((r)[0]), "=r"((r)[1]), "=r"((r)[2]), "=r"((r)[3])     \
                 : "r"(addr))

#define LDSM4T(r, addr)                                                       \
    asm volatile("ldmatrix.sync.aligned.m8n8.x4.trans.shared.b16 {%0,%1,%2,%3}, [%4];" \
                 : "=r"((r)[0]), "=r"((r)[1]), "=r"((r)[2]), "=r"((r)[3])     \
                 : "r"(addr))

#define MMA_BF16(c, a, b0, b1)                                                \
    asm volatile("mma.sync.aligned.m16n8k16.row.col.f32.bf16.bf16.f32 "       \
                 "{%0,%1,%2,%3}, {%4,%5,%6,%7}, {%8,%9}, {%0,%1,%2,%3};"      \
                 : "+f"((c)[0]), "+f"((c)[1]), "+f"((c)[2]), "+f"((c)[3])     \
                 : "r"((a)[0]), "r"((a)[1]), "r"((a)[2]), "r"((a)[3]),        \
                   "r"(b0), "r"(b1))

#define CP_ASYNC16(dst, src)                                                  \
    asm volatile("cp.async.ca.shared.global [%0], [%1], 16;"                  \
                 :: "r"(dst), "l"(src))
#define CP_COMMIT()  asm volatile("cp.async.commit_group;" ::: "memory")
#define CP_WAIT0()   asm volatile("cp.async.wait_group 0;" ::: "memory")

// Split pair (a,b) -> packed bf16x2 hi (lo16=a, hi16=b) and packed lo residue.
__device__ __forceinline__ void split2(float a, float b, uint32_t& hi, uint32_t& lo) {
    asm("cvt.rn.bf16x2.f32 %0, %1, %2;" : "=r"(hi) : "f"(b), "f"(a));
    float ahf = __uint_as_float(hi << 16);
    float bhf = __uint_as_float(hi & 0xFFFF0000u);
    float la = a - ahf, lb = b - bhf;
    asm("cvt.rn.bf16x2.f32 %0, %1, %2;" : "=r"(lo) : "f"(lb), "f"(la));
}

// ---------------------------------------------------------------------------
// Pre-split weights into bf16 hi/lo planes; zero g_cnt and g_total.
// ---------------------------------------------------------------------------
__global__ void w2bf(const float* __restrict__ w) {
    int idx = blockIdx.x * blockDim.x + threadIdx.x;
    if (idx < KDIM * HC / 2) {
        int k = (idx * 2) / HC;
        int nn = (idx * 2) % HC;
        float a = w[(nn >> 5) * (KDIM * C) + k * C + (nn & 31)];
        float b = w[((nn + 1) >> 5) * (KDIM * C) + k * C + ((nn + 1) & 31)];
        uint32_t hi, lo;
        split2(a, b, hi, lo);
        *(uint32_t*)&g_Bhi[idx * 2] = hi;
        *(uint32_t*)&g_Blo[idx * 2] = lo;
    }
    if (idx < NMAX) g_cnt[idx] = 0;
    if (idx == 0) g_total = 0;
}

// ---------------------------------------------------------------------------
// Block-specialized phase:
//  blocks [0,nGemm): tensor-core GEMM (bf16x3 fp32 emulation) + fused logits.
//  blocks [nGemm,..): in-degree histogram (RED, no return; rides gemm tail).
// ---------------------------------------------------------------------------
__global__ void __launch_bounds__(256, 2)
gemm_tc(const float* __restrict__ Ain, const float* __restrict__ att,
        const int* __restrict__ ei, int M, int e_cnt, int nGemm) {
    __shared__ __align__(16) __nv_bfloat16 sA[2][2][128][24]; // [buf][hi/lo][m][k]
    __shared__ __align__(16) __nv_bfloat16 sB[2][2][16][136]; // [buf][hi/lo][k][n]

    if (blockIdx.x >= nGemm) {
        int e = (blockIdx.x - nGemm) * blockDim.x + threadIdx.x;
        if (e < e_cnt) atomicAdd(&g_cnt[ei[e_cnt + e]], 1);
        return;
    }

    const int t = threadIdx.x;
    const int blockRow = blockIdx.x * 128;
    const int warp = t >> 5, lane = t & 31;
    const int wm = warp >> 2, wn = warp & 3;     // wn == head
    const int rquad = lane & 15, chalf = lane >> 4;
    const int grp = lane >> 2, qd = lane & 3;

    float acc[4][2][2][4];
    #pragma unroll
    for (int mt = 0; mt < 4; mt++)
        #pragma unroll
        for (int g = 0; g < 2; g++)
            #pragma unroll
            for (int s = 0; s < 2; s++)
                #pragma unroll
                for (int i = 0; i < 4; i++) acc[mt][g][s][i] = 0.f;

    const int am = t >> 1, akq = (t & 1) * 8;        // A: row, k-offset(0/8)
    const int bk = t >> 4, bnq = (t & 15) * 8;       // B: k-row, n-offset
    const int agr = blockRow + am;
    const float* aBase = Ain + (long long)agr * KDIM + akq;

    auto stage = [&](int kc, int buf) {
        int kbase = kc * 16;
        int kg = kbase + bk;
        CP_ASYNC16(s2u(&sB[buf][0][bk][bnq]), &g_Bhi[kg * HC + bnq]);
        CP_ASYNC16(s2u(&sB[buf][1][bk][bnq]), &g_Blo[kg * HC + bnq]);
        CP_COMMIT();
        float4 f0 = make_float4(0.f, 0.f, 0.f, 0.f), f1 = f0;
        if (agr < M) {
            f0 = *(const float4*)(aBase + kbase);
            f1 = *(const float4*)(aBase + kbase + 4);
        }
        uint4 hi4, lo4;
        split2(f0.x, f0.y, hi4.x, lo4.x);
        split2(f0.z, f0.w, hi4.y, lo4.y);
        split2(f1.x, f1.y, hi4.z, lo4.z);
        split2(f1.z, f1.w, hi4.w, lo4.w);
        *(uint4*)&sA[buf][0][am][akq] = hi4;
        *(uint4*)&sA[buf][1][am][akq] = lo4;
    };

    stage(0, 0);
    CP_WAIT0();
    __syncthreads();

    uint32_t uA[2][2], uB[2][2];
    #pragma unroll
    for (int b = 0; b < 2; b++)
        #pragma unroll
        for (int p = 0; p < 2; p++) {
            uA[b][p] = s2u(&sA[b][p][0][0]);
            uB[b][p] = s2u(&sB[b][p][0][0]);
        }
    uint32_t aOff = ((wm * 64 + rquad) * 24 + chalf * 8) * 2;
    uint32_t bOff = (rquad * 136 + wn * 32 + chalf * 8) * 2;

    for (int kc = 0; kc < 16; kc++) {
        int buf = kc & 1;
        if (kc + 1 < 16) stage(kc + 1, buf ^ 1);

        uint32_t ah[4][4], al[4][4], bh[2][4], bl[2][4];
        #pragma unroll
        for (int mt = 0; mt < 4; mt++) {
            LDSM4(ah[mt], uA[buf][0] + aOff + mt * 16 * 24 * 2);
            LDSM4(al[mt], uA[buf][1] + aOff + mt * 16 * 24 * 2);
        }
        #pragma unroll
        for (int g = 0; g < 2; g++) {
            LDSM4T(bh[g], uB[buf][0] + bOff + g * 16 * 2);
            LDSM4T(bl[g], uB[buf][1] + bOff + g * 16 * 2);
        }
        #pragma unroll
        for (int mt = 0; mt < 4; mt++)
            #pragma unroll
            for (int g = 0; g < 2; g++)
                #pragma unroll
                for (int s = 0; s < 2; s++) {
                    float* c = acc[mt][g][s];
                    MMA_BF16(c, ah[mt], bh[g][s * 2], bh[g][s * 2 + 1]); // hi*hi
                    MMA_BF16(c, al[mt], bh[g][s * 2], bh[g][s * 2 + 1]); // lo*hi
                    MMA_BF16(c, ah[mt], bl[g][s * 2], bl[g][s * 2 + 1]); // hi*lo
                }
        CP_WAIT0();
        __syncthreads();
    }

    // ---- Epilogue: store h + fused logits ----
    float attS[2][2][2], attD[2][2][2];
    #pragma unroll
    for (int g = 0; g < 2; g++)
        #pragma unroll
        for (int s = 0; s < 2; s++)
            #pragma unroll
            for (int i = 0; i < 2; i++) {
                int cl = g * 16 + s * 8 + qd * 2 + i;
                attS[g][s][i] = __ldg(att + wn * (2 * C) + cl);
                attD[g][s][i] = __ldg(att + wn * (2 * C) + C + cl);
            }

    #pragma unroll
    for (int mt = 0; mt < 4; mt++) {
        int r0 = blockRow + wm * 64 + mt * 16 + grp;
        int r1 = r0 + 8;
        float s1a = 0.f, s1b = 0.f, s2a = 0.f, s2b = 0.f;
        #pragma unroll
        for (int g = 0; g < 2; g++)
            #pragma unroll
            for (int s = 0; s < 2; s++) {
                const float* c = acc[mt][g][s];
                int col = wn * 32 + g * 16 + s * 8 + qd * 2;
                if (r0 < M) *(float2*)(g_h + r0 * HC + col) = make_float2(c[0], c[1]);
                if (r1 < M) *(float2*)(g_h + r1 * HC + col) = make_float2(c[2], c[3]);
                s1a = fmaf(c[0], attS[g][s][0], fmaf(c[1], attS[g][s][1], s1a));
                s1b = fmaf(c[2], attS[g][s][0], fmaf(c[3], attS[g][s][1], s1b));
                s2a = fmaf(c[0], attD[g][s][0], fmaf(c[1], attD[g][s][1], s2a));
                s2b = fmaf(c[2], attD[g][s][0], fmaf(c[3], attD[g][s][1], s2b));
            }
        s1a += __shfl_xor_sync(0xffffffffu, s1a, 1);
        s1a += __shfl_xor_sync(0xffffffffu, s1a, 2);
        s1b += __shfl_xor_sync(0xffffffffu, s1b, 1);
        s1b += __shfl_xor_sync(0xffffffffu, s1b, 2);
        s2a += __shfl_xor_sync(0xffffffffu, s2a, 1);
        s2a += __shfl_xor_sync(0xffffffffu, s2a, 2);
        s2b += __shfl_xor_sync(0xffffffffu, s2b, 1);
        s2b += __shfl_xor_sync(0xffffffffu, s2b, 2);
        if (qd == 0) {
            if (r0 < M) { g_asrc[r0 * H + wn] = s1a; g_nodeD[r0 * 8 + wn] = s2a; }
            if (r1 < M) { g_asrc[r1 * H + wn] = s1b; g_nodeD[r1 * 8 + wn] = s2b; }
        }
    }
}

// ---------------------------------------------------------------------------
// Single-pass scan: block-local Hillis-Steele + atomic global block offset.
// Writes global offs + cnt into the node record and seeds the fill cursors.
// (Arrival-order segment placement: ordering nondeterminism only perturbs
//  fp32 summation order, same class as the hist atomics.)
// ---------------------------------------------------------------------------
__global__ void scanA(int n) {
    __shared__ int sh[1024];
    __shared__ int blockOff;
    int t = threadIdx.x;
    int i = blockIdx.x * 1024 + t;
    int v = (i < n) ? g_cnt[i] : 0;
    sh[t] = v;
    __syncthreads();
    #pragma unroll
    for (int off = 1; off < 1024; off <<= 1) {
        int u = (t >= off) ? sh[t - off] : 0;
        __syncthreads();
        sh[t] += u;
        __syncthreads();
    }
    if (t == 1023) blockOff = atomicAdd(&g_total, sh[1023]);
    __syncthreads();
    if (i < n) {
        int off = blockOff + sh[t] - v;
        ((int*)g_nodeD)[i * 8 + 4] = off;
        ((int*)g_nodeD)[i * 8 + 5] = v;
        g_cur[i] = off;
    }
}

// ---------------------------------------------------------------------------
// CSR fill: slot = cursor++, store src id. (alpha is computed in agg.)
// ---------------------------------------------------------------------------
__global__ void edge_fill(const int* __restrict__ ei, int e_cnt) {
    int e = blockIdx.x * blockDim.x + threadIdx.x;
    if (e >= e_cnt) return;
    int s = ei[e], d = ei[e_cnt + e];
    int slot = atomicAdd(&g_cur[d], 1);
    g_psrc[slot] = s;
}

// ---------------------------------------------------------------------------
// Gather aggregation with on-the-fly attention: one warp per dst node.
// alpha_e = exp(LeakyReLU(a_src[src_e] + a_dst[node])); x4 unroll for MLP.
// out[d] = (sum_e h[src_e]*alpha_e) / (sum_e alpha_e + eps) + bias
// ---------------------------------------------------------------------------
__global__ void agg_kernel(float* __restrict__ out, const float* __restrict__ bias, int n) {
    int gid = blockIdx.x * blockDim.x + threadIdx.x;
    int node = gid >> 5;
    if (node >= n) return;
    int lane = gid & 31;
    int hh = lane >> 3;
    int beg = __ldg((const int*)g_nodeD + node * 8 + 4);
    int end = beg + __ldg((const int*)g_nodeD + node * 8 + 5);
    float adh = __ldg(&g_nodeD[node * 8 + hh]);       // a_dst for this head
    float4 acc = make_float4(0.f, 0.f, 0.f, 0.f);
    float asum = 0.f;
    int i = beg;
    for (; i + 4 <= end; i += 4) {
        int s0 = __ldg(&g_psrc[i]);
        int s1 = __ldg(&g_psrc[i + 1]);
        int s2 = __ldg(&g_psrc[i + 2]);
        int s3 = __ldg(&g_psrc[i + 3]);
        float l0 = __ldg(&g_asrc[s0 * 4 + hh]) + adh;
        float l1 = __ldg(&g_asrc[s1 * 4 + hh]) + adh;
        float l2 = __ldg(&g_asrc[s2 * 4 + hh]) + adh;
        float l3 = __ldg(&g_asrc[s3 * 4 + hh]) + adh;
        float4 h0 = *(const float4*)(g_h + s0 * HC + lane * 4);
        float4 h1 = *(const float4*)(g_h + s1 * HC + lane * 4);
        float4 h2 = *(const float4*)(g_h + s2 * HC + lane * 4);
        float4 h3 = *(const float4*)(g_h + s3 * HC + lane * 4);
        float a0 = __expf(l0 > 0.f ? l0 : 0.2f * l0);
        float a1 = __expf(l1 > 0.f ? l1 : 0.2f * l1);
        float a2 = __expf(l2 > 0.f ? l2 : 0.2f * l2);
        float a3 = __expf(l3 > 0.f ? l3 : 0.2f * l3);
        asum += (a0 + a1) + (a2 + a3);
        acc.x = fmaf(h0.x, a0, acc.x); acc.y = fmaf(h0.y, a0, acc.y);
        acc.z = fmaf(h0.z, a0, acc.z); acc.w = fmaf(h0.w, a0, acc.w);
        acc.x = fmaf(h1.x, a1, acc.x); acc.y = fmaf(h1.y, a1, acc.y);
        acc.z = fmaf(h1.z, a1, acc.z); acc.w = fmaf(h1.w, a1, acc.w);
        acc.x = fmaf(h2.x, a2, acc.x); acc.y = fmaf(h2.y, a2, acc.y);
        acc.z = fmaf(h2.z, a2, acc.z); acc.w = fmaf(h2.w, a2, acc.w);
        acc.x = fmaf(h3.x, a3, acc.x); acc.y = fmaf(h3.y, a3, acc.y);
        acc.z = fmaf(h3.z, a3, acc.z); acc.w = fmaf(h3.w, a3, acc.w);
    }
    for (; i < end; i++) {
        int s = __ldg(&g_psrc[i]);
        float l = __ldg(&g_asrc[s * 4 + hh]) + adh;
        float a = __expf(l > 0.f ? l : 0.2f * l);
        asum += a;
        float4 hv = *(const float4*)(g_h + s * HC + lane * 4);
        acc.x = fmaf(hv.x, a, acc.x);
        acc.y = fmaf(hv.y, a, acc.y);
        acc.z = fmaf(hv.z, a, acc.z);
        acc.w = fmaf(hv.w, a, acc.w);
    }
    float r = __frcp_rn(asum + 1e-16f);
    const float4 bv = *(const float4*)(bias + lane * 4);
    float4 o = make_float4(fmaf(acc.x, r, bv.x), fmaf(acc.y, r, bv.y),
                           fmaf(acc.z, r, bv.z), fmaf(acc.w, r, bv.w));
    *(float4*)(out + node * HC + lane * 4) = o;
}

// ---------------------------------------------------------------------------
extern "C" void kernel_launch(void* const* d_in, const int* in_sizes, int n_in,
                              void* d_out, int out_size) {
    const float* x    = (const float*)d_in[0];
    const int*   ei   = (const int*)d_in[1];
    const float* w    = (const float*)d_in[2];
    const float* att  = (const float*)d_in[3];
    const float* bias = (const float*)d_in[4];
    float* out = (float*)d_out;

    int n     = in_sizes[0] / KDIM;   // 50000
    int e_cnt = in_sizes[1] / 2;      // 800000

    w2bf<<<(NMAX + 255) / 256, 256>>>(w);
    int nGemm = (n + 127) / 128;
    int nHist = (e_cnt + 255) / 256;
    gemm_tc<<<nGemm + nHist, 256>>>(x, att, ei, n, e_cnt, nGemm);
    scanA<<<(n + 1023) / 1024, 1024>>>(n);
    edge_fill<<<(e_cnt + 255) / 256, 256>>>(ei, e_cnt);
    agg_kernel<<<(n * 32 + 255) / 256, 256>>>(out, bias, n);
}